// round 2
// baseline (speedup 1.0000x reference)
#include <cuda_runtime.h>

// GCN: out = log_softmax( agg( relu( agg(x@W1) + b1 ) @ W2 ) + b2 )
// agg uses symmetric D^-1/2 (A+I) D^-1/2 with in-degree (dst) + self loops.

#define NN 100000
#define EE 1600000
#define FF 256
#define HH 64
#define CC 16
#define NB1 98           // ceil(NN/1024)

// ---------------- scratch (static device globals; no allocation) -------------
__device__ int   g_deg[NN];
__device__ int   g_start[NN + 1];
__device__ int   g_cursor[NN];
__device__ float g_dinv[NN];
__device__ int2  g_csr[EE];              // .x = src node, .y = float bits of norm weight
__device__ float g_h1[(size_t)NN * HH];  // x @ W1
__device__ float g_x2[(size_t)NN * HH];  // relu(agg1 + b1)
__device__ float g_z [(size_t)NN * CC];  // x2 @ W2
__device__ int   g_bsum[128];
__device__ int   g_is64;                 // edge_index stored as int64 (vs int32)

// ---------------- packed f32x2 helpers (Blackwell FFMA2) ---------------------
__device__ __forceinline__ unsigned long long f32x2_dup(float v) {
    unsigned long long r;
    asm("mov.b64 %0, {%1, %1};" : "=l"(r) : "f"(v));
    return r;
}
__device__ __forceinline__ void ffma2(unsigned long long& d,
                                      unsigned long long a,
                                      unsigned long long b) {
    asm("fma.rn.f32x2 %0, %1, %2, %0;" : "+l"(d) : "l"(a), "l"(b));
}
__device__ __forceinline__ float2 f32x2_unpack(unsigned long long v) {
    float2 r;
    asm("mov.b64 {%0, %1}, %2;" : "=f"(r.x), "=f"(r.y) : "l"(v));
    return r;
}

// ---------------- edge dtype handling ----------------------------------------
__device__ __forceinline__ int edge_at(const void* ei, long long idx) {
    if (g_is64) return (int)((const long long*)ei)[idx];
    return ((const int*)ei)[idx];
}

// ---------------- zero + dtype detect ----------------------------------------
__global__ void k_zero(const int* __restrict__ ei32) {
    int i = blockIdx.x * blockDim.x + threadIdx.x;
    if (i < NN) g_deg[i] = 0;
    if (blockIdx.x == 0 && threadIdx.x == 0) {
        int s = 0;
        // if int64 little-endian, every odd 32-bit word is 0 (values < 2^17)
        for (int j = 0; j < 64; ++j) s |= ei32[2 * j + 1];
        g_is64 = (s == 0) ? 1 : 0;
    }
}

__global__ void k_hist(const void* __restrict__ ei) {
    int e = blockIdx.x * blockDim.x + threadIdx.x;
    if (e >= EE) return;
    int d = edge_at(ei, (long long)EE + e);   // dst row
    atomicAdd(&g_deg[d], 1);
}

// ---------------- scan (with fused dinv) -------------------------------------
__global__ void k_scan1() {
    __shared__ int s[1024];
    int t = threadIdx.x;
    int i = blockIdx.x * 1024 + t;
    int v = (i < NN) ? g_deg[i] : 0;
    if (i < NN) g_dinv[i] = rsqrtf((float)(v + 1));   // +1 self loop
    s[t] = v;
    __syncthreads();
    for (int off = 1; off < 1024; off <<= 1) {
        int add = (t >= off) ? s[t - off] : 0;
        __syncthreads();
        s[t] += add;
        __syncthreads();
    }
    if (i < NN) g_start[i] = s[t] - v;        // exclusive within block
    if (t == 1023) g_bsum[blockIdx.x] = s[t]; // block total
}

__global__ void k_scan2() {
    __shared__ int sb[128];
    int t = threadIdx.x;
    sb[t] = (t < NB1) ? g_bsum[t] : 0;
    __syncthreads();
    if (t == 0) {
        int run = 0;
        for (int b = 0; b < NB1; ++b) { int v = sb[b]; sb[b] = run; run += v; }
        g_start[NN] = EE;
    }
    __syncthreads();
    if (t < NB1) g_bsum[t] = sb[t];
}

__global__ void k_scan3() {
    int i = blockIdx.x * 1024 + threadIdx.x;
    if (i < NN) {
        int v = g_start[i] + g_bsum[blockIdx.x];
        g_start[i]  = v;
        g_cursor[i] = v;
    }
}

__global__ void k_scatter(const void* __restrict__ ei) {
    int e = blockIdx.x * blockDim.x + threadIdx.x;
    if (e >= EE) return;
    int s = edge_at(ei, e);
    int d = edge_at(ei, (long long)EE + e);
    float w = g_dinv[s] * g_dinv[d];
    int pos = atomicAdd(&g_cursor[d], 1);
    g_csr[pos] = make_int2(s, __float_as_int(w));
}

// ---------------- GEMM1: h1 = x @ W1  (100000x256 @ 256x64) ------------------
// 128-row x 64-col tile, 256 threads, each thread 8 rows x 4 cols.
// Row-pairs are accumulated in packed f32x2 registers via fma.rn.f32x2:
//   acc[i][c] holds (rows tr+2i, tr+2i+1) for column tc+c.
// XsT is k-major with row-stride 130 floats (8B aligned, 2-way store conflicts
// at worst) so a row-pair A operand is a single LDS.64.
#define PADR 130
__global__ void __launch_bounds__(256) k_gemm1(const float* __restrict__ x,
                                               const float* __restrict__ W1) {
    __shared__ __align__(16) float XsT[64][PADR];   // XsT[k][r], r < 128
    __shared__ __align__(16) float Ws[64][64];      // Ws[k][c]
    int t = threadIdx.x;
    int row0 = blockIdx.x * 128;
    int rg = t >> 4, cg = t & 15;
    int tr = rg * 8;          // 8 rows per thread
    int tc = cg * 4;          // 4 cols per thread

    unsigned long long acc[4][4];
#pragma unroll
    for (int i = 0; i < 4; ++i)
#pragma unroll
        for (int c = 0; c < 4; ++c) acc[i][c] = 0ull;

    for (int k0 = 0; k0 < FF; k0 += 64) {
        // load X tile (128 rows x 64 k): coalesced global, transposed smem store
#pragma unroll
        for (int it = 0; it < 32; ++it) {
            int fid = t + it * 256;
            int r = fid >> 6;
            int k = fid & 63;
            int gr = row0 + r;
            XsT[k][r] = (gr < NN) ? x[(size_t)gr * FF + k0 + k] : 0.f;
        }
        // load W tile (64 k x 64 c)
#pragma unroll
        for (int it = 0; it < 4; ++it) {
            int fid = t + it * 256;
            int k = fid >> 4;
            int c = (fid & 15) << 2;
            *(float4*)&Ws[k][c] = *(const float4*)&W1[(size_t)(k0 + k) * HH + c];
        }
        __syncthreads();
#pragma unroll 8
        for (int kk = 0; kk < 64; ++kk) {
            float4 b = *(const float4*)&Ws[kk][tc];
            unsigned long long b0 = f32x2_dup(b.x);
            unsigned long long b1 = f32x2_dup(b.y);
            unsigned long long b2 = f32x2_dup(b.z);
            unsigned long long b3 = f32x2_dup(b.w);
            unsigned long long a0 = *(const unsigned long long*)&XsT[kk][tr + 0];
            unsigned long long a1 = *(const unsigned long long*)&XsT[kk][tr + 2];
            unsigned long long a2 = *(const unsigned long long*)&XsT[kk][tr + 4];
            unsigned long long a3 = *(const unsigned long long*)&XsT[kk][tr + 6];
            ffma2(acc[0][0], a0, b0); ffma2(acc[0][1], a0, b1);
            ffma2(acc[0][2], a0, b2); ffma2(acc[0][3], a0, b3);
            ffma2(acc[1][0], a1, b0); ffma2(acc[1][1], a1, b1);
            ffma2(acc[1][2], a1, b2); ffma2(acc[1][3], a1, b3);
            ffma2(acc[2][0], a2, b0); ffma2(acc[2][1], a2, b1);
            ffma2(acc[2][2], a2, b2); ffma2(acc[2][3], a2, b3);
            ffma2(acc[3][0], a3, b0); ffma2(acc[3][1], a3, b1);
            ffma2(acc[3][2], a3, b2); ffma2(acc[3][3], a3, b3);
        }
        __syncthreads();
    }

#pragma unroll
    for (int i = 0; i < 4; ++i) {
        float2 c0 = f32x2_unpack(acc[i][0]);
        float2 c1 = f32x2_unpack(acc[i][1]);
        float2 c2 = f32x2_unpack(acc[i][2]);
        float2 c3 = f32x2_unpack(acc[i][3]);
        int r_lo = row0 + tr + 2 * i;
        int r_hi = r_lo + 1;
        if (r_lo < NN)
            *(float4*)&g_h1[(size_t)r_lo * HH + tc] = make_float4(c0.x, c1.x, c2.x, c3.x);
        if (r_hi < NN)
            *(float4*)&g_h1[(size_t)r_hi * HH + tc] = make_float4(c0.y, c1.y, c2.y, c3.y);
    }
}

// ---------------- agg1: x2 = relu( D^-1/2 (A+I) D^-1/2 h1 + b1 ) ------------
// one warp per node, lane l handles dims [2l, 2l+1] as float2
__global__ void k_agg1(const float* __restrict__ b1) {
    int gw = (blockIdx.x * blockDim.x + threadIdx.x) >> 5;
    if (gw >= NN) return;
    int lane = threadIdx.x & 31;
    int n = gw;
    const float2* h1 = (const float2*)g_h1;

    float di = g_dinv[n];
    float selfw = di * di;
    float2 hv = h1[(size_t)n * 32 + lane];
    float2 acc = make_float2(hv.x * selfw, hv.y * selfw);

    int e0 = g_start[n], e1 = g_start[n + 1];
#pragma unroll 2
    for (int e = e0; e < e1; ++e) {
        int2  ce = g_csr[e];                    // broadcast 8B load
        float w  = __int_as_float(ce.y);
        float2 v = h1[(size_t)ce.x * 32 + lane];
        acc.x += w * v.x;
        acc.y += w * v.y;
    }
    float2 bb = ((const float2*)b1)[lane];
    acc.x = fmaxf(acc.x + bb.x, 0.f);
    acc.y = fmaxf(acc.y + bb.y, 0.f);
    ((float2*)g_x2)[(size_t)n * 32 + lane] = acc;
}

// ---------------- GEMM2: z = x2 @ W2  (100000x64 @ 64x16) -------------------
__global__ void k_gemm2(const float* __restrict__ W2) {
    __shared__ float Xs[64][65];
    __shared__ float Ws[64][16];
    int t = threadIdx.x;
    int n0 = blockIdx.x * 64;
    int r  = t >> 2;            // node within tile
    int c0 = (t & 3) << 2;      // col group

#pragma unroll
    for (int it = 0; it < 16; ++it) {
        int fid = t + it * 256;
        int rr = fid >> 6;
        int k  = fid & 63;
        int gn = n0 + rr;
        Xs[rr][k] = (gn < NN) ? g_x2[(size_t)gn * HH + k] : 0.f;
    }
    {
        int k = t >> 2;
        int c = (t & 3) << 2;
        *(float4*)&Ws[k][c] = *(const float4*)&W2[(size_t)k * CC + c];
    }
    __syncthreads();

    float acc0 = 0.f, acc1 = 0.f, acc2 = 0.f, acc3 = 0.f;
#pragma unroll
    for (int k = 0; k < 64; ++k) {
        float a = Xs[r][k];
        float4 b = *(const float4*)&Ws[k][c0];
        acc0 += a * b.x; acc1 += a * b.y; acc2 += a * b.z; acc3 += a * b.w;
    }
    int gn = n0 + r;
    if (gn < NN)
        *(float4*)&g_z[(size_t)gn * CC + c0] = make_float4(acc0, acc1, acc2, acc3);
}

// ---------------- agg2 + bias + log_softmax ---------------------------------
__global__ void k_agg2(const float* __restrict__ b2, float* __restrict__ out) {
    int gw = (blockIdx.x * blockDim.x + threadIdx.x) >> 5;
    if (gw >= NN) return;
    int lane = threadIdx.x & 31;
    int c = lane & 15;
    int n = gw;

    float di = g_dinv[n];
    float acc = g_z[(size_t)n * CC + c] * (di * di);

    int e0 = g_start[n], e1 = g_start[n + 1];
#pragma unroll 2
    for (int e = e0; e < e1; ++e) {
        int2  ce = g_csr[e];
        float w  = __int_as_float(ce.y);
        acc += w * g_z[(size_t)ce.x * CC + c];
    }
    acc += b2[c];

    // log_softmax over 16 dims within each half-warp (halves are identical)
    float m = acc;
#pragma unroll
    for (int o = 8; o >= 1; o >>= 1)
        m = fmaxf(m, __shfl_xor_sync(0xffffffffu, m, o, 16));
    float ex = expf(acc - m);
    float s = ex;
#pragma unroll
    for (int o = 8; o >= 1; o >>= 1)
        s += __shfl_xor_sync(0xffffffffu, s, o, 16);
    float res = acc - m - logf(s);

    if (lane < 16) out[(size_t)n * CC + c] = res;
}

// ---------------- launch -----------------------------------------------------
extern "C" void kernel_launch(void* const* d_in, const int* in_sizes, int n_in,
                              void* d_out, int out_size) {
    const float* x  = (const float*)d_in[0];
    const void*  ei = d_in[1];
    const float* W1 = (const float*)d_in[2];
    const float* b1 = (const float*)d_in[3];
    const float* W2 = (const float*)d_in[4];
    const float* b2 = (const float*)d_in[5];
    float* out = (float*)d_out;

    k_zero  <<<(NN + 255) / 256, 256>>>((const int*)ei);
    k_hist  <<<(EE + 255) / 256, 256>>>(ei);
    k_scan1 <<<NB1, 1024>>>();
    k_scan2 <<<1, 128>>>();
    k_scan3 <<<NB1, 1024>>>();
    k_scatter<<<(EE + 255) / 256, 256>>>(ei);
    k_gemm1 <<<(NN + 127) / 128, 256>>>(x, W1);
    k_agg1  <<<12500, 256>>>(b1);
    k_gemm2 <<<(NN + 63) / 64, 256>>>(W2);
    k_agg2  <<<12500, 256>>>(b2, out);
}

// round 4
// speedup vs baseline: 1.1636x; 1.1636x over previous
#include <cuda_runtime.h>
#include <cuda_bf16.h>
#include <cstdint>

// GCN: out = log_softmax( agg( relu( agg(x@W1) + b1 ) @ W2 ) + b2 )
// agg uses symmetric D^-1/2 (A+I) D^-1/2 with in-degree (dst) + self loops.
// GEMM1 uses warp-level HMMA (mma.sync bf16, 3-pass split, fp32 accum).

#define NN 100000
#define EE 1600000
#define FF 256
#define HH 64
#define CC 16
#define NB1 98           // ceil(NN/1024)

// ---------------- scratch (static device globals; no allocation) -------------
__device__ int   g_deg[NN];
__device__ int   g_start[NN + 1];
__device__ int   g_cursor[NN];
__device__ float g_dinv[NN];
__device__ int2  g_csr[EE];              // .x = src node, .y = float bits of norm weight
__device__ float g_h1[(size_t)NN * HH];  // x @ W1
__device__ float g_x2[(size_t)NN * HH];  // relu(agg1 + b1)
__device__ float g_z [(size_t)NN * CC];  // x2 @ W2
__device__ int   g_bsum[128];
__device__ int   g_is64;                 // edge_index stored as int64 (vs int32)
__device__ __nv_bfloat16 g_w1t_hi[HH * FF];  // W1^T split, [64][256] bf16 (k-contig)
__device__ __nv_bfloat16 g_w1t_lo[HH * FF];

// ---------------- edge dtype handling ----------------------------------------
__device__ __forceinline__ int edge_at(const void* ei, long long idx) {
    if (g_is64) return (int)((const long long*)ei)[idx];
    return ((const int*)ei)[idx];
}

// ---------------- W1^T bf16 split prep ---------------------------------------
__global__ void k_wsplit(const float* __restrict__ W1) {
    int idx = blockIdx.x * blockDim.x + threadIdx.x;   // over [64][256]
    if (idx >= HH * FF) return;
    int c = idx >> 8;       // out col  (0..63)
    int k = idx & 255;      // k        (0..255)
    float v = W1[(size_t)k * HH + c];
    __nv_bfloat16 hi = __float2bfloat16(v);
    __nv_bfloat16 lo = __float2bfloat16(v - __bfloat162float(hi));
    g_w1t_hi[c * FF + k] = hi;
    g_w1t_lo[c * FF + k] = lo;
}

// ---------------- zero + dtype detect ----------------------------------------
__global__ void k_zero(const int* __restrict__ ei32) {
    int i = blockIdx.x * blockDim.x + threadIdx.x;
    if (i < NN) g_deg[i] = 0;
    if (blockIdx.x == 0 && threadIdx.x == 0) {
        int s = 0;
        for (int j = 0; j < 64; ++j) s |= ei32[2 * j + 1];
        g_is64 = (s == 0) ? 1 : 0;
    }
}

__global__ void k_hist(const void* __restrict__ ei) {
    int e = blockIdx.x * blockDim.x + threadIdx.x;
    if (e >= EE) return;
    int d = edge_at(ei, (long long)EE + e);
    atomicAdd(&g_deg[d], 1);
}

// ---------------- scan (with fused dinv) -------------------------------------
__global__ void k_scan1() {
    __shared__ int s[1024];
    int t = threadIdx.x;
    int i = blockIdx.x * 1024 + t;
    int v = (i < NN) ? g_deg[i] : 0;
    if (i < NN) g_dinv[i] = rsqrtf((float)(v + 1));
    s[t] = v;
    __syncthreads();
    for (int off = 1; off < 1024; off <<= 1) {
        int add = (t >= off) ? s[t - off] : 0;
        __syncthreads();
        s[t] += add;
        __syncthreads();
    }
    if (i < NN) g_start[i] = s[t] - v;
    if (t == 1023) g_bsum[blockIdx.x] = s[t];
}

__global__ void k_scan2() {
    __shared__ int sb[128];
    int t = threadIdx.x;
    sb[t] = (t < NB1) ? g_bsum[t] : 0;
    __syncthreads();
    if (t == 0) {
        int run = 0;
        for (int b = 0; b < NB1; ++b) { int v = sb[b]; sb[b] = run; run += v; }
        g_start[NN] = EE;
    }
    __syncthreads();
    if (t < NB1) g_bsum[t] = sb[t];
}

__global__ void k_scan3() {
    int i = blockIdx.x * 1024 + threadIdx.x;
    if (i < NN) {
        int v = g_start[i] + g_bsum[blockIdx.x];
        g_start[i]  = v;
        g_cursor[i] = v;
    }
}

__global__ void k_scatter(const void* __restrict__ ei) {
    int e = blockIdx.x * blockDim.x + threadIdx.x;
    if (e >= EE) return;
    int s = edge_at(ei, e);
    int d = edge_at(ei, (long long)EE + e);
    float w = g_dinv[s] * g_dinv[d];
    int pos = atomicAdd(&g_cursor[d], 1);
    g_csr[pos] = make_int2(s, __float_as_int(w));
}

// ---------------- GEMM1 (HMMA): h1 = x @ W1 ----------------------------------
// 128x64 tile per 256-thread block; warp = 32 rows x 32 cols.
// bf16 3-pass split: h1 = Ahi*Bhi + Ahi*Blo + Alo*Bhi (fp32 accum).
// smem rows padded to 68 u32 (136 bf16) -> conflict-free fragment LDS.
#define KC   128            // K chunk
#define ROWU 68             // u32 per smem row (64 data + 4 pad)
#define SA   (128 * ROWU)   // u32 count of one A tile
#define SB   (64 * ROWU)
#define SM_AHI 0
#define SM_ALO SA
#define SM_BHI (2 * SA)
#define SM_BLO (2 * SA + SB)
#define SMEM_U32 (2 * SA + 2 * SB)
#define SMEM_BYTES (SMEM_U32 * 4)

__device__ __forceinline__ void mma_bf16(float& d0, float& d1, float& d2, float& d3,
                                         uint32_t a0, uint32_t a1, uint32_t a2, uint32_t a3,
                                         uint32_t b0, uint32_t b1) {
    asm volatile(
        "mma.sync.aligned.m16n8k16.row.col.f32.bf16.bf16.f32 "
        "{%0,%1,%2,%3}, {%4,%5,%6,%7}, {%8,%9}, {%0,%1,%2,%3};"
        : "+f"(d0), "+f"(d1), "+f"(d2), "+f"(d3)
        : "r"(a0), "r"(a1), "r"(a2), "r"(a3), "r"(b0), "r"(b1));
}

__global__ void __launch_bounds__(256, 2) k_gemm1(const float* __restrict__ x) {
    extern __shared__ __align__(16) uint32_t sm[];
    int t = threadIdx.x;
    int wid = t >> 5;
    int lane = t & 31;
    int g   = lane >> 2;     // group id (0..7)
    int tig = lane & 3;      // thread in group
    int row0 = blockIdx.x * 128;
    int mrow0 = (wid >> 1) * 32;   // warp row base within tile
    int ncol0 = (wid & 1) * 32;    // warp col base within tile

    float acc[2][4][4];
#pragma unroll
    for (int mt = 0; mt < 2; ++mt)
#pragma unroll
        for (int nt = 0; nt < 4; ++nt)
#pragma unroll
            for (int i = 0; i < 4; ++i) acc[mt][nt][i] = 0.f;

    const uint32_t* wh = (const uint32_t*)g_w1t_hi;   // [64][128] u32
    const uint32_t* wl = (const uint32_t*)g_w1t_lo;

    for (int k0 = 0; k0 < FF; k0 += KC) {
        // ---- fill A hi/lo: x[row0..+128][k0..+128] fp32 -> bf16 split ----
#pragma unroll
        for (int i = 0; i < 16; ++i) {
            int idx = t + i * 256;           // float4 index over [128][32]
            int row = idx >> 5;
            int c4  = (idx & 31) << 2;       // col in floats
            int gr  = row0 + row;
            float4 v = (gr < NN) ? *(const float4*)&x[(size_t)gr * FF + k0 + c4]
                                 : make_float4(0.f, 0.f, 0.f, 0.f);
            __nv_bfloat162 h01 = __floats2bfloat162_rn(v.x, v.y);
            __nv_bfloat162 h23 = __floats2bfloat162_rn(v.z, v.w);
            __nv_bfloat162 l01 = __floats2bfloat162_rn(v.x - __bfloat162float(__low2bfloat16(h01)),
                                                       v.y - __bfloat162float(__high2bfloat16(h01)));
            __nv_bfloat162 l23 = __floats2bfloat162_rn(v.z - __bfloat162float(__low2bfloat16(h23)),
                                                       v.w - __bfloat162float(__high2bfloat16(h23)));
            int base = row * ROWU + (c4 >> 1);
            sm[SM_AHI + base]     = *(uint32_t*)&h01;
            sm[SM_AHI + base + 1] = *(uint32_t*)&h23;
            sm[SM_ALO + base]     = *(uint32_t*)&l01;
            sm[SM_ALO + base + 1] = *(uint32_t*)&l23;
        }
        // ---- fill B hi/lo: w1t[0..64][k0..+128] ----
#pragma unroll
        for (int i = 0; i < 16; ++i) {
            int idx = t + i * 256;           // u32 index over [64][64]
            int row = idx >> 6;
            int cp  = idx & 63;
            sm[SM_BHI + row * ROWU + cp] = wh[row * 128 + (k0 >> 1) + cp];
            sm[SM_BLO + row * ROWU + cp] = wl[row * 128 + (k0 >> 1) + cp];
        }
        __syncthreads();

        // ---- compute: 8 k-steps of m16n8k16 ----
#pragma unroll
        for (int ks = 0; ks < 8; ++ks) {
            int kb = ks * 8;                 // k base in u32 (16 bf16)
            uint32_t ahi[2][4], alo[2][4];
#pragma unroll
            for (int mt = 0; mt < 2; ++mt) {
                int r = mrow0 + mt * 16 + g;
                int b0 = r * ROWU + kb + tig;
                int b1 = (r + 8) * ROWU + kb + tig;
                ahi[mt][0] = sm[SM_AHI + b0];
                ahi[mt][1] = sm[SM_AHI + b1];
                ahi[mt][2] = sm[SM_AHI + b0 + 4];
                ahi[mt][3] = sm[SM_AHI + b1 + 4];
                alo[mt][0] = sm[SM_ALO + b0];
                alo[mt][1] = sm[SM_ALO + b1];
                alo[mt][2] = sm[SM_ALO + b0 + 4];
                alo[mt][3] = sm[SM_ALO + b1 + 4];
            }
#pragma unroll
            for (int nt = 0; nt < 4; ++nt) {
                int n = ncol0 + nt * 8 + g;
                int bo = n * ROWU + kb + tig;
                uint32_t bhi0 = sm[SM_BHI + bo], bhi1 = sm[SM_BHI + bo + 4];
                uint32_t blo0 = sm[SM_BLO + bo], blo1 = sm[SM_BLO + bo + 4];
#pragma unroll
                for (int mt = 0; mt < 2; ++mt) {
                    float* a = acc[mt][nt];
                    mma_bf16(a[0], a[1], a[2], a[3],
                             ahi[mt][0], ahi[mt][1], ahi[mt][2], ahi[mt][3], bhi0, bhi1);
                    mma_bf16(a[0], a[1], a[2], a[3],
                             ahi[mt][0], ahi[mt][1], ahi[mt][2], ahi[mt][3], blo0, blo1);
                    mma_bf16(a[0], a[1], a[2], a[3],
                             alo[mt][0], alo[mt][1], alo[mt][2], alo[mt][3], bhi0, bhi1);
                }
            }
        }
        __syncthreads();
    }

    // ---- store D fragments ----
#pragma unroll
    for (int mt = 0; mt < 2; ++mt) {
#pragma unroll
        for (int nt = 0; nt < 4; ++nt) {
            int r = row0 + mrow0 + mt * 16 + g;
            int c = ncol0 + nt * 8 + tig * 2;
            float* a = acc[mt][nt];
            if (r < NN)     *(float2*)&g_h1[(size_t)r * HH + c]       = make_float2(a[0], a[1]);
            if (r + 8 < NN) *(float2*)&g_h1[(size_t)(r + 8) * HH + c] = make_float2(a[2], a[3]);
        }
    }
}

// ---------------- agg1: x2 = relu( D^-1/2 (A+I) D^-1/2 h1 + b1 ) ------------
__global__ void k_agg1(const float* __restrict__ b1) {
    int gw = (blockIdx.x * blockDim.x + threadIdx.x) >> 5;
    if (gw >= NN) return;
    int lane = threadIdx.x & 31;
    int n = gw;
    const float2* h1 = (const float2*)g_h1;

    float di = g_dinv[n];
    float selfw = di * di;
    float2 hv = h1[(size_t)n * 32 + lane];
    float2 acc = make_float2(hv.x * selfw, hv.y * selfw);

    int e0 = g_start[n], e1 = g_start[n + 1];
#pragma unroll 2
    for (int e = e0; e < e1; ++e) {
        int2  ce = g_csr[e];
        float w  = __int_as_float(ce.y);
        float2 v = h1[(size_t)ce.x * 32 + lane];
        acc.x += w * v.x;
        acc.y += w * v.y;
    }
    float2 bb = ((const float2*)b1)[lane];
    acc.x = fmaxf(acc.x + bb.x, 0.f);
    acc.y = fmaxf(acc.y + bb.y, 0.f);
    ((float2*)g_x2)[(size_t)n * 32 + lane] = acc;
}

// ---------------- GEMM2: z = x2 @ W2  (100000x64 @ 64x16) -------------------
__global__ void k_gemm2(const float* __restrict__ W2) {
    __shared__ float Xs[64][65];
    __shared__ float Ws[64][16];
    int t = threadIdx.x;
    int n0 = blockIdx.x * 64;
    int r  = t >> 2;
    int c0 = (t & 3) << 2;

#pragma unroll
    for (int it = 0; it < 16; ++it) {
        int fid = t + it * 256;
        int rr = fid >> 6;
        int k  = fid & 63;
        int gn = n0 + rr;
        Xs[rr][k] = (gn < NN) ? g_x2[(size_t)gn * HH + k] : 0.f;
    }
    {
        int k = t >> 2;
        int c = (t & 3) << 2;
        *(float4*)&Ws[k][c] = *(const float4*)&W2[(size_t)k * CC + c];
    }
    __syncthreads();

    float acc0 = 0.f, acc1 = 0.f, acc2 = 0.f, acc3 = 0.f;
#pragma unroll
    for (int k = 0; k < 64; ++k) {
        float a = Xs[r][k];
        float4 b = *(const float4*)&Ws[k][c0];
        acc0 += a * b.x; acc1 += a * b.y; acc2 += a * b.z; acc3 += a * b.w;
    }
    int gn = n0 + r;
    if (gn < NN)
        *(float4*)&g_z[(size_t)gn * CC + c0] = make_float4(acc0, acc1, acc2, acc3);
}

// ---------------- agg2 + bias + log_softmax ---------------------------------
__global__ void k_agg2(const float* __restrict__ b2, float* __restrict__ out) {
    int gw = (blockIdx.x * blockDim.x + threadIdx.x) >> 5;
    if (gw >= NN) return;
    int lane = threadIdx.x & 31;
    int c = lane & 15;
    int n = gw;

    float di = g_dinv[n];
    float acc = g_z[(size_t)n * CC + c] * (di * di);

    int e0 = g_start[n], e1 = g_start[n + 1];
#pragma unroll 2
    for (int e = e0; e < e1; ++e) {
        int2  ce = g_csr[e];
        float w  = __int_as_float(ce.y);
        acc += w * g_z[(size_t)ce.x * CC + c];
    }
    acc += b2[c];

    float m = acc;
#pragma unroll
    for (int o = 8; o >= 1; o >>= 1)
        m = fmaxf(m, __shfl_xor_sync(0xffffffffu, m, o, 16));
    float ex = expf(acc - m);
    float s = ex;
#pragma unroll
    for (int o = 8; o >= 1; o >>= 1)
        s += __shfl_xor_sync(0xffffffffu, s, o, 16);
    float res = acc - m - logf(s);

    if (lane < 16) out[(size_t)n * CC + c] = res;
}

// ---------------- launch -----------------------------------------------------
extern "C" void kernel_launch(void* const* d_in, const int* in_sizes, int n_in,
                              void* d_out, int out_size) {
    const float* x  = (const float*)d_in[0];
    const void*  ei = d_in[1];
    const float* W1 = (const float*)d_in[2];
    const float* b1 = (const float*)d_in[3];
    const float* W2 = (const float*)d_in[4];
    const float* b2 = (const float*)d_in[5];
    float* out = (float*)d_out;

    cudaFuncSetAttribute(k_gemm1, cudaFuncAttributeMaxDynamicSharedMemorySize, SMEM_BYTES);

    k_wsplit<<<(HH * FF + 255) / 256, 256>>>(W1);            // 0
    k_zero  <<<(NN + 255) / 256, 256>>>((const int*)ei);     // 1
    k_hist  <<<(EE + 255) / 256, 256>>>(ei);                 // 2
    k_gemm1 <<<(NN + 127) / 128, 256, SMEM_BYTES>>>(x);      // 3  <- ncu captures this
    k_scan1 <<<NB1, 1024>>>();                               // 4
    k_scan2 <<<1, 128>>>();                                  // 5
    k_scan3 <<<NB1, 1024>>>();                               // 6
    k_scatter<<<(EE + 255) / 256, 256>>>(ei);                // 7
    k_agg1  <<<12500, 256>>>(b1);                            // 8
    k_gemm2 <<<(NN + 63) / 64, 256>>>(W2);                   // 9
    k_agg2  <<<12500, 256>>>(b2, out);                       // 10
}

// round 5
// speedup vs baseline: 1.2501x; 1.0744x over previous
#include <cuda_runtime.h>
#include <cuda_bf16.h>
#include <cstdint>

// GCN: out = log_softmax( agg( relu( agg(x@W1) + b1 ) @ W2 ) + b2 )
// agg uses symmetric D^-1/2 (A+I) D^-1/2 with in-degree (dst) + self loops.
// GEMM1 uses warp-level HMMA (mma.sync bf16, 3-pass split, fp32 accum).
// Edge-chain (hist/scan/scatter) runs on a parallel graph branch vs GEMM1.

#define NN 100000
#define EE 1600000
#define FF 256
#define HH 64
#define CC 16
#define NB1 98           // ceil(NN/1024)

// ---------------- scratch (static device globals; no allocation) -------------
__device__ int   g_deg[NN];
__device__ int   g_start[NN + 1];
__device__ int   g_cursor[NN];
__device__ float g_dinv[NN];
__device__ int2  g_csr[EE];              // .x = src node, .y = float bits of norm weight
__device__ float g_h1[(size_t)NN * HH];  // x @ W1
__device__ float g_x2[(size_t)NN * HH];  // relu(agg1 + b1)
__device__ float g_z [(size_t)NN * CC];  // x2 @ W2
__device__ int   g_bsum[128];
__device__ int   g_is64;                 // edge_index stored as int64 (vs int32)
__device__ __nv_bfloat16 g_w1t_hi[HH * FF];  // W1^T split, [64][256] bf16 (k-contig)
__device__ __nv_bfloat16 g_w1t_lo[HH * FF];

// ---------------- edge dtype handling ----------------------------------------
__device__ __forceinline__ int edge_at(const void* ei, long long idx) {
    if (g_is64) return (int)((const long long*)ei)[idx];
    return ((const int*)ei)[idx];
}

// ---------------- W1^T bf16 split prep ---------------------------------------
__global__ void k_wsplit(const float* __restrict__ W1) {
    int idx = blockIdx.x * blockDim.x + threadIdx.x;   // over [64][256]
    if (idx >= HH * FF) return;
    int c = idx >> 8;       // out col  (0..63)
    int k = idx & 255;      // k        (0..255)
    float v = W1[(size_t)k * HH + c];
    __nv_bfloat16 hi = __float2bfloat16(v);
    __nv_bfloat16 lo = __float2bfloat16(v - __bfloat162float(hi));
    g_w1t_hi[c * FF + k] = hi;
    g_w1t_lo[c * FF + k] = lo;
}

// ---------------- zero + dtype detect ----------------------------------------
__global__ void k_zero(const int* __restrict__ ei32) {
    int i = blockIdx.x * blockDim.x + threadIdx.x;
    if (i < NN) g_deg[i] = 0;
    if (blockIdx.x == 0 && threadIdx.x == 0) {
        int s = 0;
        for (int j = 0; j < 64; ++j) s |= ei32[2 * j + 1];
        g_is64 = (s == 0) ? 1 : 0;
    }
}

__global__ void k_hist(const void* __restrict__ ei) {
    int e = blockIdx.x * blockDim.x + threadIdx.x;
    if (e >= EE) return;
    int d = edge_at(ei, (long long)EE + e);
    atomicAdd(&g_deg[d], 1);
}

// ---------------- scan (with fused dinv) -------------------------------------
__global__ void k_scan1() {
    __shared__ int s[1024];
    int t = threadIdx.x;
    int i = blockIdx.x * 1024 + t;
    int v = (i < NN) ? g_deg[i] : 0;
    if (i < NN) g_dinv[i] = rsqrtf((float)(v + 1));
    s[t] = v;
    __syncthreads();
    for (int off = 1; off < 1024; off <<= 1) {
        int add = (t >= off) ? s[t - off] : 0;
        __syncthreads();
        s[t] += add;
        __syncthreads();
    }
    if (i < NN) g_start[i] = s[t] - v;
    if (t == 1023) g_bsum[blockIdx.x] = s[t];
}

__global__ void k_scan2() {
    __shared__ int sb[128];
    int t = threadIdx.x;
    sb[t] = (t < NB1) ? g_bsum[t] : 0;
    __syncthreads();
    if (t == 0) {
        int run = 0;
        for (int b = 0; b < NB1; ++b) { int v = sb[b]; sb[b] = run; run += v; }
        g_start[NN] = EE;
    }
    __syncthreads();
    if (t < NB1) g_bsum[t] = sb[t];
}

__global__ void k_scan3() {
    int i = blockIdx.x * 1024 + threadIdx.x;
    if (i < NN) {
        int v = g_start[i] + g_bsum[blockIdx.x];
        g_start[i]  = v;
        g_cursor[i] = v;
    }
}

__global__ void k_scatter(const void* __restrict__ ei) {
    int e = blockIdx.x * blockDim.x + threadIdx.x;
    if (e >= EE) return;
    int s = edge_at(ei, e);
    int d = edge_at(ei, (long long)EE + e);
    float w = g_dinv[s] * g_dinv[d];
    int pos = atomicAdd(&g_cursor[d], 1);
    g_csr[pos] = make_int2(s, __float_as_int(w));
}

// ---------------- GEMM1 (HMMA): h1 = x @ W1 ----------------------------------
// 128x64 tile per 256-thread block; warp = 32 rows x 32 cols.
// bf16 3-pass split: h1 = Ahi*Bhi + Ahi*Blo + Alo*Bhi (fp32 accum).
// K chunked at 64 -> 54 KB smem -> 2 CTAs/SM for latency hiding.
#define KC   64             // K chunk (floats)
#define ROWU 36             // u32 per smem row (32 data + 4 pad)
#define SA   (128 * ROWU)   // u32 count of one A tile
#define SB   (64 * ROWU)
#define SM_AHI 0
#define SM_ALO SA
#define SM_BHI (2 * SA)
#define SM_BLO (2 * SA + SB)
#define SMEM_U32 (2 * SA + 2 * SB)
#define SMEM_BYTES (SMEM_U32 * 4)

__device__ __forceinline__ void mma_bf16(float& d0, float& d1, float& d2, float& d3,
                                         uint32_t a0, uint32_t a1, uint32_t a2, uint32_t a3,
                                         uint32_t b0, uint32_t b1) {
    asm volatile(
        "mma.sync.aligned.m16n8k16.row.col.f32.bf16.bf16.f32 "
        "{%0,%1,%2,%3}, {%4,%5,%6,%7}, {%8,%9}, {%0,%1,%2,%3};"
        : "+f"(d0), "+f"(d1), "+f"(d2), "+f"(d3)
        : "r"(a0), "r"(a1), "r"(a2), "r"(a3), "r"(b0), "r"(b1));
}

__global__ void __launch_bounds__(256, 2) k_gemm1(const float* __restrict__ x) {
    extern __shared__ __align__(16) uint32_t sm[];
    int t = threadIdx.x;
    int wid = t >> 5;
    int lane = t & 31;
    int g   = lane >> 2;     // group id (0..7)
    int tig = lane & 3;      // thread in group
    int row0 = blockIdx.x * 128;
    int mrow0 = (wid >> 1) * 32;   // warp row base within tile
    int ncol0 = (wid & 1) * 32;    // warp col base within tile

    float acc[2][4][4];
#pragma unroll
    for (int mt = 0; mt < 2; ++mt)
#pragma unroll
        for (int nt = 0; nt < 4; ++nt)
#pragma unroll
            for (int i = 0; i < 4; ++i) acc[mt][nt][i] = 0.f;

    const uint32_t* wh = (const uint32_t*)g_w1t_hi;   // [64][128] u32
    const uint32_t* wl = (const uint32_t*)g_w1t_lo;

    for (int k0 = 0; k0 < FF; k0 += KC) {
        // ---- fill A hi/lo: x[row0..+128][k0..+64] fp32 -> bf16 split ----
#pragma unroll
        for (int i = 0; i < 8; ++i) {
            int idx = t + i * 256;           // float4 index over [128][16]
            int row = idx >> 4;
            int c4  = (idx & 15) << 2;       // col in floats
            int gr  = row0 + row;
            float4 v = (gr < NN) ? *(const float4*)&x[(size_t)gr * FF + k0 + c4]
                                 : make_float4(0.f, 0.f, 0.f, 0.f);
            __nv_bfloat162 h01 = __floats2bfloat162_rn(v.x, v.y);
            __nv_bfloat162 h23 = __floats2bfloat162_rn(v.z, v.w);
            __nv_bfloat162 l01 = __floats2bfloat162_rn(v.x - __bfloat162float(__low2bfloat16(h01)),
                                                       v.y - __bfloat162float(__high2bfloat16(h01)));
            __nv_bfloat162 l23 = __floats2bfloat162_rn(v.z - __bfloat162float(__low2bfloat16(h23)),
                                                       v.w - __bfloat162float(__high2bfloat16(h23)));
            int base = row * ROWU + (c4 >> 1);
            sm[SM_AHI + base]     = *(uint32_t*)&h01;
            sm[SM_AHI + base + 1] = *(uint32_t*)&h23;
            sm[SM_ALO + base]     = *(uint32_t*)&l01;
            sm[SM_ALO + base + 1] = *(uint32_t*)&l23;
        }
        // ---- fill B hi/lo: w1t[0..64][k0..+64] ----
#pragma unroll
        for (int i = 0; i < 8; ++i) {
            int idx = t + i * 256;           // u32 index over [64][32]
            int row = idx >> 5;
            int cp  = idx & 31;
            sm[SM_BHI + row * ROWU + cp] = wh[row * 128 + (k0 >> 1) + cp];
            sm[SM_BLO + row * ROWU + cp] = wl[row * 128 + (k0 >> 1) + cp];
        }
        __syncthreads();

        // ---- compute: 4 k-steps of m16n8k16 ----
#pragma unroll
        for (int ks = 0; ks < 4; ++ks) {
            int kb = ks * 8;                 // k base in u32 (16 bf16)
            uint32_t ahi[2][4], alo[2][4];
#pragma unroll
            for (int mt = 0; mt < 2; ++mt) {
                int r = mrow0 + mt * 16 + g;
                int b0 = r * ROWU + kb + tig;
                int b1 = (r + 8) * ROWU + kb + tig;
                ahi[mt][0] = sm[SM_AHI + b0];
                ahi[mt][1] = sm[SM_AHI + b1];
                ahi[mt][2] = sm[SM_AHI + b0 + 4];
                ahi[mt][3] = sm[SM_AHI + b1 + 4];
                alo[mt][0] = sm[SM_ALO + b0];
                alo[mt][1] = sm[SM_ALO + b1];
                alo[mt][2] = sm[SM_ALO + b0 + 4];
                alo[mt][3] = sm[SM_ALO + b1 + 4];
            }
#pragma unroll
            for (int nt = 0; nt < 4; ++nt) {
                int n = ncol0 + nt * 8 + g;
                int bo = n * ROWU + kb + tig;
                uint32_t bhi0 = sm[SM_BHI + bo], bhi1 = sm[SM_BHI + bo + 4];
                uint32_t blo0 = sm[SM_BLO + bo], blo1 = sm[SM_BLO + bo + 4];
#pragma unroll
                for (int mt = 0; mt < 2; ++mt) {
                    float* a = acc[mt][nt];
                    mma_bf16(a[0], a[1], a[2], a[3],
                             ahi[mt][0], ahi[mt][1], ahi[mt][2], ahi[mt][3], bhi0, bhi1);
                    mma_bf16(a[0], a[1], a[2], a[3],
                             ahi[mt][0], ahi[mt][1], ahi[mt][2], ahi[mt][3], blo0, blo1);
                    mma_bf16(a[0], a[1], a[2], a[3],
                             alo[mt][0], alo[mt][1], alo[mt][2], alo[mt][3], bhi0, bhi1);
                }
            }
        }
        __syncthreads();
    }

    // ---- store D fragments ----
#pragma unroll
    for (int mt = 0; mt < 2; ++mt) {
#pragma unroll
        for (int nt = 0; nt < 4; ++nt) {
            int r = row0 + mrow0 + mt * 16 + g;
            int c = ncol0 + nt * 8 + tig * 2;
            float* a = acc[mt][nt];
            if (r < NN)     *(float2*)&g_h1[(size_t)r * HH + c]       = make_float2(a[0], a[1]);
            if (r + 8 < NN) *(float2*)&g_h1[(size_t)(r + 8) * HH + c] = make_float2(a[2], a[3]);
        }
    }
}

// ---------------- agg1: x2 = relu( D^-1/2 (A+I) D^-1/2 h1 + b1 ) ------------
__global__ void k_agg1(const float* __restrict__ b1) {
    int gw = (blockIdx.x * blockDim.x + threadIdx.x) >> 5;
    if (gw >= NN) return;
    int lane = threadIdx.x & 31;
    int n = gw;
    const float2* h1 = (const float2*)g_h1;

    float di = g_dinv[n];
    float selfw = di * di;
    float2 hv = h1[(size_t)n * 32 + lane];
    float2 acc = make_float2(hv.x * selfw, hv.y * selfw);

    int e0 = g_start[n], e1 = g_start[n + 1];
#pragma unroll 2
    for (int e = e0; e < e1; ++e) {
        int2  ce = g_csr[e];
        float w  = __int_as_float(ce.y);
        float2 v = h1[(size_t)ce.x * 32 + lane];
        acc.x += w * v.x;
        acc.y += w * v.y;
    }
    float2 bb = ((const float2*)b1)[lane];
    acc.x = fmaxf(acc.x + bb.x, 0.f);
    acc.y = fmaxf(acc.y + bb.y, 0.f);
    ((float2*)g_x2)[(size_t)n * 32 + lane] = acc;
}

// ---------------- GEMM2: z = x2 @ W2  (100000x64 @ 64x16) -------------------
__global__ void k_gemm2(const float* __restrict__ W2) {
    __shared__ float Xs[64][65];
    __shared__ float Ws[64][16];
    int t = threadIdx.x;
    int n0 = blockIdx.x * 64;
    int r  = t >> 2;
    int c0 = (t & 3) << 2;

#pragma unroll
    for (int it = 0; it < 16; ++it) {
        int fid = t + it * 256;
        int rr = fid >> 6;
        int k  = fid & 63;
        int gn = n0 + rr;
        Xs[rr][k] = (gn < NN) ? g_x2[(size_t)gn * HH + k] : 0.f;
    }
    {
        int k = t >> 2;
        int c = (t & 3) << 2;
        *(float4*)&Ws[k][c] = *(const float4*)&W2[(size_t)k * CC + c];
    }
    __syncthreads();

    float acc0 = 0.f, acc1 = 0.f, acc2 = 0.f, acc3 = 0.f;
#pragma unroll
    for (int k = 0; k < 64; ++k) {
        float a = Xs[r][k];
        float4 b = *(const float4*)&Ws[k][c0];
        acc0 += a * b.x; acc1 += a * b.y; acc2 += a * b.z; acc3 += a * b.w;
    }
    int gn = n0 + r;
    if (gn < NN)
        *(float4*)&g_z[(size_t)gn * CC + c0] = make_float4(acc0, acc1, acc2, acc3);
}

// ---------------- agg2 + bias + log_softmax ---------------------------------
__global__ void k_agg2(const float* __restrict__ b2, float* __restrict__ out) {
    int gw = (blockIdx.x * blockDim.x + threadIdx.x) >> 5;
    if (gw >= NN) return;
    int lane = threadIdx.x & 31;
    int c = lane & 15;
    int n = gw;

    float di = g_dinv[n];
    float acc = g_z[(size_t)n * CC + c] * (di * di);

    int e0 = g_start[n], e1 = g_start[n + 1];
#pragma unroll 2
    for (int e = e0; e < e1; ++e) {
        int2  ce = g_csr[e];
        float w  = __int_as_float(ce.y);
        acc += w * g_z[(size_t)ce.x * CC + c];
    }
    acc += b2[c];

    float m = acc;
#pragma unroll
    for (int o = 8; o >= 1; o >>= 1)
        m = fmaxf(m, __shfl_xor_sync(0xffffffffu, m, o, 16));
    float ex = expf(acc - m);
    float s = ex;
#pragma unroll
    for (int o = 8; o >= 1; o >>= 1)
        s += __shfl_xor_sync(0xffffffffu, s, o, 16);
    float res = acc - m - logf(s);

    if (lane < 16) out[(size_t)n * CC + c] = res;
}

// ---------------- launch -----------------------------------------------------
// Fork a side stream inside capture: edge-chain runs concurrently with GEMM1.
extern "C" void kernel_launch(void* const* d_in, const int* in_sizes, int n_in,
                              void* d_out, int out_size) {
    const float* x  = (const float*)d_in[0];
    const void*  ei = d_in[1];
    const float* W1 = (const float*)d_in[2];
    const float* b1 = (const float*)d_in[3];
    const float* W2 = (const float*)d_in[4];
    const float* b2 = (const float*)d_in[5];
    float* out = (float*)d_out;

    cudaFuncSetAttribute(k_gemm1, cudaFuncAttributeMaxDynamicSharedMemorySize, SMEM_BYTES);

    cudaStream_t side;
    cudaEvent_t evFork, evJoin;
    cudaStreamCreateWithFlags(&side, cudaStreamNonBlocking);
    cudaEventCreateWithFlags(&evFork, cudaEventDisableTiming);
    cudaEventCreateWithFlags(&evJoin, cudaEventDisableTiming);

    // fork: side stream handles the edge chain
    cudaEventRecord(evFork, cudaStreamPerThread);
    cudaStreamWaitEvent(side, evFork, 0);

    k_zero   <<<(NN + 255) / 256, 256, 0, side>>>((const int*)ei);
    k_hist   <<<(EE + 255) / 256, 256, 0, side>>>(ei);
    k_scan1  <<<NB1, 1024, 0, side>>>();
    k_scan2  <<<1, 128, 0, side>>>();
    k_scan3  <<<NB1, 1024, 0, side>>>();
    k_scatter<<<(EE + 255) / 256, 256, 0, side>>>(ei);
    cudaEventRecord(evJoin, side);

    // main branch: feature transform
    k_wsplit<<<(HH * FF + 255) / 256, 256>>>(W1);
    k_gemm1 <<<(NN + 127) / 128, 256, SMEM_BYTES>>>(x);

    // join, then the dependent tail
    cudaStreamWaitEvent(cudaStreamPerThread, evJoin, 0);
    k_agg1  <<<12500, 256>>>(b1);
    k_gemm2 <<<(NN + 63) / 64, 256>>>(W2);
    k_agg2  <<<12500, 256>>>(b2, out);
}

// round 6
// speedup vs baseline: 1.4745x; 1.1795x over previous
#include <cuda_runtime.h>
#include <cuda_bf16.h>
#include <cstdint>

// GCN: out = log_softmax( agg( relu( agg(x@W1) + b1 ) @ W2 ) + b2 )
// agg uses symmetric D^-1/2 (A+I) D^-1/2 with in-degree (dst) + self loops.
// GEMM1 uses warp-level HMMA (mma.sync bf16, 3-pass split, fp32 accum).
// Edge-chain (hist/scan/scatter) runs on a parallel graph branch vs GEMM1.

#define NN 100000
#define EE 1600000
#define FF 256
#define HH 64
#define CC 16
#define NB1 98           // ceil(NN/1024)

// ---------------- scratch (static device globals; no allocation) -------------
__device__ int   g_deg[NN];
__device__ int   g_start[NN + 1];
__device__ int   g_cursor[NN];
__device__ float g_dinv[NN];
__device__ int2  g_csr[EE];              // .x = src node, .y = float bits of norm weight
__device__ float g_h1[(size_t)NN * HH];  // x @ W1
__device__ float g_x2[(size_t)NN * HH];  // relu(agg1 + b1)
__device__ float g_z [(size_t)NN * CC];  // x2 @ W2
__device__ int   g_bsum[128];
__device__ int   g_is64;                 // edge_index stored as int64 (vs int32)
__device__ __nv_bfloat16 g_w1t_hi[HH * FF];  // W1^T split, [64][256] bf16 (k-contig)
__device__ __nv_bfloat16 g_w1t_lo[HH * FF];

// ---------------- edge dtype handling ----------------------------------------
__device__ __forceinline__ int edge_at(const void* ei, long long idx) {
    if (g_is64) return (int)((const long long*)ei)[idx];
    return ((const int*)ei)[idx];
}

// ---------------- W1^T bf16 split prep ---------------------------------------
__global__ void k_wsplit(const float* __restrict__ W1) {
    int idx = blockIdx.x * blockDim.x + threadIdx.x;   // over [64][256]
    if (idx >= HH * FF) return;
    int c = idx >> 8;       // out col  (0..63)
    int k = idx & 255;      // k        (0..255)
    float v = W1[(size_t)k * HH + c];
    __nv_bfloat16 hi = __float2bfloat16(v);
    __nv_bfloat16 lo = __float2bfloat16(v - __bfloat162float(hi));
    g_w1t_hi[c * FF + k] = hi;
    g_w1t_lo[c * FF + k] = lo;
}

// ---------------- zero + dtype detect ----------------------------------------
__global__ void k_zero(const int* __restrict__ ei32) {
    int i = blockIdx.x * blockDim.x + threadIdx.x;
    if (i < NN) g_deg[i] = 0;
    if (blockIdx.x == 0 && threadIdx.x == 0) {
        int s = 0;
        for (int j = 0; j < 64; ++j) s |= ei32[2 * j + 1];
        g_is64 = (s == 0) ? 1 : 0;
    }
}

__global__ void k_hist(const void* __restrict__ ei) {
    int e = blockIdx.x * blockDim.x + threadIdx.x;
    if (e >= EE) return;
    int d = edge_at(ei, (long long)EE + e);
    atomicAdd(&g_deg[d], 1);
}

// ---------------- scan (with fused dinv) -------------------------------------
__global__ void k_scan1() {
    __shared__ int s[1024];
    int t = threadIdx.x;
    int i = blockIdx.x * 1024 + t;
    int v = (i < NN) ? g_deg[i] : 0;
    if (i < NN) g_dinv[i] = rsqrtf((float)(v + 1));
    s[t] = v;
    __syncthreads();
    for (int off = 1; off < 1024; off <<= 1) {
        int add = (t >= off) ? s[t - off] : 0;
        __syncthreads();
        s[t] += add;
        __syncthreads();
    }
    if (i < NN) g_start[i] = s[t] - v;
    if (t == 1023) g_bsum[blockIdx.x] = s[t];
}

__global__ void k_scan2() {
    __shared__ int sb[128];
    int t = threadIdx.x;
    sb[t] = (t < NB1) ? g_bsum[t] : 0;
    __syncthreads();
    if (t == 0) {
        int run = 0;
        for (int b = 0; b < NB1; ++b) { int v = sb[b]; sb[b] = run; run += v; }
        g_start[NN] = EE;
    }
    __syncthreads();
    if (t < NB1) g_bsum[t] = sb[t];
}

__global__ void k_scan3() {
    int i = blockIdx.x * 1024 + threadIdx.x;
    if (i < NN) {
        int v = g_start[i] + g_bsum[blockIdx.x];
        g_start[i]  = v;
        g_cursor[i] = v;
    }
}

__global__ void k_scatter(const void* __restrict__ ei) {
    int e = blockIdx.x * blockDim.x + threadIdx.x;
    if (e >= EE) return;
    int s = edge_at(ei, e);
    int d = edge_at(ei, (long long)EE + e);
    float w = g_dinv[s] * g_dinv[d];
    int pos = atomicAdd(&g_cursor[d], 1);
    g_csr[pos] = make_int2(s, __float_as_int(w));
}

// ---------------- GEMM1 (HMMA): h1 = x @ W1 ----------------------------------
// 128x64 tile per 256-thread block; warp = 32 rows x 32 cols.
// bf16 3-pass split: h1 = Ahi*Bhi + Ahi*Blo + Alo*Bhi (fp32 accum).
// K chunked at 64 -> 54 KB smem -> 2 CTAs/SM for latency hiding.
#define KC   64             // K chunk (floats)
#define ROWU 36             // u32 per smem row (32 data + 4 pad)
#define SA   (128 * ROWU)   // u32 count of one A tile
#define SB   (64 * ROWU)
#define SM_AHI 0
#define SM_ALO SA
#define SM_BHI (2 * SA)
#define SM_BLO (2 * SA + SB)
#define SMEM_U32 (2 * SA + 2 * SB)
#define SMEM_BYTES (SMEM_U32 * 4)

__device__ __forceinline__ void mma_bf16(float& d0, float& d1, float& d2, float& d3,
                                         uint32_t a0, uint32_t a1, uint32_t a2, uint32_t a3,
                                         uint32_t b0, uint32_t b1) {
    asm volatile(
        "mma.sync.aligned.m16n8k16.row.col.f32.bf16.bf16.f32 "
        "{%0,%1,%2,%3}, {%4,%5,%6,%7}, {%8,%9}, {%0,%1,%2,%3};"
        : "+f"(d0), "+f"(d1), "+f"(d2), "+f"(d3)
        : "r"(a0), "r"(a1), "r"(a2), "r"(a3), "r"(b0), "r"(b1));
}

__global__ void __launch_bounds__(256, 2) k_gemm1(const float* __restrict__ x) {
    extern __shared__ __align__(16) uint32_t sm[];
    int t = threadIdx.x;
    int wid = t >> 5;
    int lane = t & 31;
    int g   = lane >> 2;     // group id (0..7)
    int tig = lane & 3;      // thread in group
    int row0 = blockIdx.x * 128;
    int mrow0 = (wid >> 1) * 32;   // warp row base within tile
    int ncol0 = (wid & 1) * 32;    // warp col base within tile

    float acc[2][4][4];
#pragma unroll
    for (int mt = 0; mt < 2; ++mt)
#pragma unroll
        for (int nt = 0; nt < 4; ++nt)
#pragma unroll
            for (int i = 0; i < 4; ++i) acc[mt][nt][i] = 0.f;

    const uint32_t* wh = (const uint32_t*)g_w1t_hi;   // [64][128] u32
    const uint32_t* wl = (const uint32_t*)g_w1t_lo;

    for (int k0 = 0; k0 < FF; k0 += KC) {
        // ---- fill A hi/lo: x[row0..+128][k0..+64] fp32 -> bf16 split ----
#pragma unroll
        for (int i = 0; i < 8; ++i) {
            int idx = t + i * 256;           // float4 index over [128][16]
            int row = idx >> 4;
            int c4  = (idx & 15) << 2;       // col in floats
            int gr  = row0 + row;
            float4 v = (gr < NN) ? *(const float4*)&x[(size_t)gr * FF + k0 + c4]
                                 : make_float4(0.f, 0.f, 0.f, 0.f);
            __nv_bfloat162 h01 = __floats2bfloat162_rn(v.x, v.y);
            __nv_bfloat162 h23 = __floats2bfloat162_rn(v.z, v.w);
            __nv_bfloat162 l01 = __floats2bfloat162_rn(v.x - __bfloat162float(__low2bfloat16(h01)),
                                                       v.y - __bfloat162float(__high2bfloat16(h01)));
            __nv_bfloat162 l23 = __floats2bfloat162_rn(v.z - __bfloat162float(__low2bfloat16(h23)),
                                                       v.w - __bfloat162float(__high2bfloat16(h23)));
            int base = row * ROWU + (c4 >> 1);
            sm[SM_AHI + base]     = *(uint32_t*)&h01;
            sm[SM_AHI + base + 1] = *(uint32_t*)&h23;
            sm[SM_ALO + base]     = *(uint32_t*)&l01;
            sm[SM_ALO + base + 1] = *(uint32_t*)&l23;
        }
        // ---- fill B hi/lo: w1t[0..64][k0..+64] ----
#pragma unroll
        for (int i = 0; i < 8; ++i) {
            int idx = t + i * 256;           // u32 index over [64][32]
            int row = idx >> 5;
            int cp  = idx & 31;
            sm[SM_BHI + row * ROWU + cp] = wh[row * 128 + (k0 >> 1) + cp];
            sm[SM_BLO + row * ROWU + cp] = wl[row * 128 + (k0 >> 1) + cp];
        }
        __syncthreads();

        // ---- compute: 4 k-steps of m16n8k16 ----
#pragma unroll
        for (int ks = 0; ks < 4; ++ks) {
            int kb = ks * 8;                 // k base in u32 (16 bf16)
            uint32_t ahi[2][4], alo[2][4];
#pragma unroll
            for (int mt = 0; mt < 2; ++mt) {
                int r = mrow0 + mt * 16 + g;
                int b0 = r * ROWU + kb + tig;
                int b1 = (r + 8) * ROWU + kb + tig;
                ahi[mt][0] = sm[SM_AHI + b0];
                ahi[mt][1] = sm[SM_AHI + b1];
                ahi[mt][2] = sm[SM_AHI + b0 + 4];
                ahi[mt][3] = sm[SM_AHI + b1 + 4];
                alo[mt][0] = sm[SM_ALO + b0];
                alo[mt][1] = sm[SM_ALO + b1];
                alo[mt][2] = sm[SM_ALO + b0 + 4];
                alo[mt][3] = sm[SM_ALO + b1 + 4];
            }
#pragma unroll
            for (int nt = 0; nt < 4; ++nt) {
                int n = ncol0 + nt * 8 + g;
                int bo = n * ROWU + kb + tig;
                uint32_t bhi0 = sm[SM_BHI + bo], bhi1 = sm[SM_BHI + bo + 4];
                uint32_t blo0 = sm[SM_BLO + bo], blo1 = sm[SM_BLO + bo + 4];
#pragma unroll
                for (int mt = 0; mt < 2; ++mt) {
                    float* a = acc[mt][nt];
                    mma_bf16(a[0], a[1], a[2], a[3],
                             ahi[mt][0], ahi[mt][1], ahi[mt][2], ahi[mt][3], bhi0, bhi1);
                    mma_bf16(a[0], a[1], a[2], a[3],
                             ahi[mt][0], ahi[mt][1], ahi[mt][2], ahi[mt][3], blo0, blo1);
                    mma_bf16(a[0], a[1], a[2], a[3],
                             alo[mt][0], alo[mt][1], alo[mt][2], alo[mt][3], bhi0, bhi1);
                }
            }
        }
        __syncthreads();
    }

    // ---- store D fragments ----
#pragma unroll
    for (int mt = 0; mt < 2; ++mt) {
#pragma unroll
        for (int nt = 0; nt < 4; ++nt) {
            int r = row0 + mrow0 + mt * 16 + g;
            int c = ncol0 + nt * 8 + tig * 2;
            float* a = acc[mt][nt];
            if (r < NN)     *(float2*)&g_h1[(size_t)r * HH + c]       = make_float2(a[0], a[1]);
            if (r + 8 < NN) *(float2*)&g_h1[(size_t)(r + 8) * HH + c] = make_float2(a[2], a[3]);
        }
    }
}

// ---------------- agg1: x2 = relu( D^-1/2 (A+I) D^-1/2 h1 + b1 ) ------------
// 2 nodes per warp: half-warp (16 lanes) per node, lane handles 4 dims (float4).
// Two independent edge loops run in lockstep -> 2x memory-level parallelism.
__global__ void k_agg1(const float* __restrict__ b1) {
    int warp = (blockIdx.x * blockDim.x + threadIdx.x) >> 5;
    int lane = threadIdx.x & 31;
    int half = lane >> 4;            // 0 or 1
    int hl   = lane & 15;            // lane within half
    int n = warp * 2 + half;
    if (n >= NN) return;

    const float4* h1 = (const float4*)g_h1;

    float di = g_dinv[n];
    float selfw = di * di;
    float4 hv = h1[(size_t)n * 16 + hl];
    float4 acc = make_float4(hv.x * selfw, hv.y * selfw, hv.z * selfw, hv.w * selfw);

    int e  = g_start[n];
    int eE = g_start[n + 1];
#pragma unroll 4
    for (; e < eE; ++e) {
        int2  ce = __ldg(&g_csr[e]);                 // 8B broadcast within half
        float w  = __int_as_float(ce.y);
        float4 v = h1[(size_t)ce.x * 16 + hl];
        acc.x += w * v.x;  acc.y += w * v.y;
        acc.z += w * v.z;  acc.w += w * v.w;
    }
    float4 bb = ((const float4*)b1)[hl];
    acc.x = fmaxf(acc.x + bb.x, 0.f);
    acc.y = fmaxf(acc.y + bb.y, 0.f);
    acc.z = fmaxf(acc.z + bb.z, 0.f);
    acc.w = fmaxf(acc.w + bb.w, 0.f);
    ((float4*)g_x2)[(size_t)n * 16 + hl] = acc;
}

// ---------------- GEMM2: z = x2 @ W2  (100000x64 @ 64x16) -------------------
__global__ void k_gemm2(const float* __restrict__ W2) {
    __shared__ float Xs[64][65];
    __shared__ float Ws[64][16];
    int t = threadIdx.x;
    int n0 = blockIdx.x * 64;
    int r  = t >> 2;
    int c0 = (t & 3) << 2;

#pragma unroll
    for (int it = 0; it < 16; ++it) {
        int fid = t + it * 256;
        int rr = fid >> 6;
        int k  = fid & 63;
        int gn = n0 + rr;
        Xs[rr][k] = (gn < NN) ? g_x2[(size_t)gn * HH + k] : 0.f;
    }
    {
        int k = t >> 2;
        int c = (t & 3) << 2;
        *(float4*)&Ws[k][c] = *(const float4*)&W2[(size_t)k * CC + c];
    }
    __syncthreads();

    float acc0 = 0.f, acc1 = 0.f, acc2 = 0.f, acc3 = 0.f;
#pragma unroll
    for (int k = 0; k < 64; ++k) {
        float a = Xs[r][k];
        float4 b = *(const float4*)&Ws[k][c0];
        acc0 += a * b.x; acc1 += a * b.y; acc2 += a * b.z; acc3 += a * b.w;
    }
    int gn = n0 + r;
    if (gn < NN)
        *(float4*)&g_z[(size_t)gn * CC + c0] = make_float4(acc0, acc1, acc2, acc3);
}

// ---------------- agg2 + bias + log_softmax ---------------------------------
// 2 nodes per warp: half-warp per node, lane handles 1 of 16 dims.
__global__ void k_agg2(const float* __restrict__ b2, float* __restrict__ out) {
    int warp = (blockIdx.x * blockDim.x + threadIdx.x) >> 5;
    int lane = threadIdx.x & 31;
    int half = lane >> 4;
    int c    = lane & 15;
    int n = warp * 2 + half;
    if (n >= NN) return;

    float di = g_dinv[n];
    float acc = g_z[(size_t)n * CC + c] * (di * di);

    int e  = g_start[n];
    int eE = g_start[n + 1];
#pragma unroll 4
    for (; e < eE; ++e) {
        int2  ce = __ldg(&g_csr[e]);
        float w  = __int_as_float(ce.y);
        acc += w * g_z[(size_t)ce.x * CC + c];
    }
    acc += b2[c];

    // log_softmax over 16 dims within the half-warp
    float m = acc;
#pragma unroll
    for (int o = 8; o >= 1; o >>= 1)
        m = fmaxf(m, __shfl_xor_sync(0xffffffffu, m, o, 16));
    float ex = expf(acc - m);
    float s = ex;
#pragma unroll
    for (int o = 8; o >= 1; o >>= 1)
        s += __shfl_xor_sync(0xffffffffu, s, o, 16);
    out[(size_t)n * CC + c] = acc - m - logf(s);
}

// ---------------- launch -----------------------------------------------------
// Call order chosen so k_gemm1 is the 4th launch (ncu profiles index 3).
// Stream assignment (not call order) defines graph dependencies.
extern "C" void kernel_launch(void* const* d_in, const int* in_sizes, int n_in,
                              void* d_out, int out_size) {
    const float* x  = (const float*)d_in[0];
    const void*  ei = d_in[1];
    const float* W1 = (const float*)d_in[2];
    const float* b1 = (const float*)d_in[3];
    const float* W2 = (const float*)d_in[4];
    const float* b2 = (const float*)d_in[5];
    float* out = (float*)d_out;

    cudaFuncSetAttribute(k_gemm1, cudaFuncAttributeMaxDynamicSharedMemorySize, SMEM_BYTES);

    cudaStream_t side;
    cudaEvent_t evFork, evJoin;
    cudaStreamCreateWithFlags(&side, cudaStreamNonBlocking);
    cudaEventCreateWithFlags(&evFork, cudaEventDisableTiming);
    cudaEventCreateWithFlags(&evJoin, cudaEventDisableTiming);

    // fork: side stream handles the edge chain
    cudaEventRecord(evFork, cudaStreamPerThread);
    cudaStreamWaitEvent(side, evFork, 0);

    k_zero   <<<(NN + 255) / 256, 256, 0, side>>>((const int*)ei);   // 0
    k_hist   <<<(EE + 255) / 256, 256, 0, side>>>(ei);               // 1
    k_wsplit <<<(HH * FF + 255) / 256, 256>>>(W1);                   // 2 (main)
    k_gemm1  <<<(NN + 127) / 128, 256, SMEM_BYTES>>>(x);             // 3 (main) <- profiled
    k_scan1  <<<NB1, 1024, 0, side>>>();                             // 4
    k_scan2  <<<1, 128, 0, side>>>();                                // 5
    k_scan3  <<<NB1, 1024, 0, side>>>();                             // 6
    k_scatter<<<(EE + 255) / 256, 256, 0, side>>>(ei);               // 7
    cudaEventRecord(evJoin, side);

    // join, then the dependent tail
    cudaStreamWaitEvent(cudaStreamPerThread, evJoin, 0);
    k_agg1  <<<(NN / 2 + 255) / 256 * 32, 256>>>(b1);                // 8
    k_gemm2 <<<(NN + 63) / 64, 256>>>(W2);                           // 9
    k_agg2  <<<(NN / 2 + 255) / 256 * 32, 256>>>(b2, out);           // 10
}

// round 7
// speedup vs baseline: 1.5431x; 1.0465x over previous
#include <cuda_runtime.h>
#include <cuda_bf16.h>
#include <cstdint>

// GCN: out = log_softmax( agg( relu( agg(x@W1) + b1 ) @ W2 ) + b2 )
// agg uses symmetric D^-1/2 (A+I) D^-1/2 with in-degree (dst) + self loops.
// Norm factored: agg(h)[d] = dinv[d] * ( sum_{s in N(d)} dinv[s]*h[s] + dinv[d]*h[d] )
// -> CSR stores src only (4B/edge); layer-2 uses prescaled z' = dinv*z.

#define NN 100000
#define EE 1600000
#define FF 256
#define HH 64
#define CC 16
#define NB1 98           // ceil(NN/1024)

// ---------------- scratch (static device globals; no allocation) -------------
__device__ int   g_deg[NN];
__device__ int   g_start[NN + 1];
__device__ int   g_cursor[NN];
__device__ float g_dinv[NN];
__device__ int   g_csr[EE];              // src node only
__device__ float g_h1[(size_t)NN * HH];  // x @ W1
__device__ float g_x2[(size_t)NN * HH];  // relu(agg1 + b1)
__device__ float g_z [(size_t)NN * CC];  // dinv * (x2 @ W2)   (prescaled z')
__device__ int   g_bsum[128];
__device__ int   g_is64;                 // edge_index stored as int64 (vs int32)
__device__ __nv_bfloat16 g_w1t_hi[HH * FF];  // W1^T split, [64][256] bf16 (k-contig)
__device__ __nv_bfloat16 g_w1t_lo[HH * FF];

// ---------------- W1^T bf16 split prep ---------------------------------------
__global__ void k_wsplit(const float* __restrict__ W1) {
    int idx = blockIdx.x * blockDim.x + threadIdx.x;   // over [64][256]
    if (idx >= HH * FF) return;
    int c = idx >> 8;       // out col  (0..63)
    int k = idx & 255;      // k        (0..255)
    float v = W1[(size_t)k * HH + c];
    __nv_bfloat16 hi = __float2bfloat16(v);
    __nv_bfloat16 lo = __float2bfloat16(v - __bfloat162float(hi));
    g_w1t_hi[c * FF + k] = hi;
    g_w1t_lo[c * FF + k] = lo;
}

// ---------------- zero + dtype detect ----------------------------------------
__global__ void k_zero(const int* __restrict__ ei32) {
    int i = blockIdx.x * blockDim.x + threadIdx.x;
    if (i < NN) g_deg[i] = 0;
    if (blockIdx.x == 0 && threadIdx.x == 0) {
        int s = 0;
        // int64 little-endian: odd 32-bit words are 0 (values < 2^17)
        for (int j = 0; j < 64; ++j) s |= ei32[2 * j + 1];
        g_is64 = (s == 0) ? 1 : 0;
    }
}

// 2 edges per thread, 16B/8B vector loads of the dst row
__global__ void k_hist(const void* __restrict__ ei) {
    int i = blockIdx.x * blockDim.x + threadIdx.x;   // pair index
    if (i >= EE / 2) return;
    int d0, d1;
    if (g_is64) {
        longlong2 p = ((const longlong2*)((const long long*)ei + EE))[i];
        d0 = (int)p.x; d1 = (int)p.y;
    } else {
        int2 p = ((const int2*)((const int*)ei + EE))[i];
        d0 = p.x; d1 = p.y;
    }
    atomicAdd(&g_deg[d0], 1);
    atomicAdd(&g_deg[d1], 1);
}

// ---------------- scan (with fused dinv) -------------------------------------
__global__ void k_scan1() {
    __shared__ int s[1024];
    int t = threadIdx.x;
    int i = blockIdx.x * 1024 + t;
    int v = (i < NN) ? g_deg[i] : 0;
    if (i < NN) g_dinv[i] = rsqrtf((float)(v + 1));   // +1 self loop
    s[t] = v;
    __syncthreads();
    for (int off = 1; off < 1024; off <<= 1) {
        int add = (t >= off) ? s[t - off] : 0;
        __syncthreads();
        s[t] += add;
        __syncthreads();
    }
    if (i < NN) g_start[i] = s[t] - v;        // exclusive within block
    if (t == 1023) g_bsum[blockIdx.x] = s[t]; // block total
}

// fused scan2+scan3: each block sums bsum[0..b) itself (L2-hot, tiny)
__global__ void k_scan23() {
    __shared__ int pref;
    int b = blockIdx.x;
    int t = threadIdx.x;
    if (t == 0) {
        int run = 0;
#pragma unroll 4
        for (int j = 0; j < b; ++j) run += g_bsum[j];
        pref = run;
        if (b == 0) g_start[NN] = EE;
    }
    __syncthreads();
    int i = b * 1024 + t;
    if (i < NN) {
        int v = g_start[i] + pref;
        g_start[i]  = v;
        g_cursor[i] = v;
    }
}

// 2 edges per thread; no dinv gathers, 4B csr writes
__global__ void k_scatter(const void* __restrict__ ei) {
    int i = blockIdx.x * blockDim.x + threadIdx.x;   // pair index
    if (i >= EE / 2) return;
    int s0, s1, d0, d1;
    if (g_is64) {
        longlong2 sp = ((const longlong2*)ei)[i];
        longlong2 dp = ((const longlong2*)((const long long*)ei + EE))[i];
        s0 = (int)sp.x; s1 = (int)sp.y; d0 = (int)dp.x; d1 = (int)dp.y;
    } else {
        int2 sp = ((const int2*)ei)[i];
        int2 dp = ((const int2*)((const int*)ei + EE))[i];
        s0 = sp.x; s1 = sp.y; d0 = dp.x; d1 = dp.y;
    }
    int p0 = atomicAdd(&g_cursor[d0], 1);
    g_csr[p0] = s0;
    int p1 = atomicAdd(&g_cursor[d1], 1);
    g_csr[p1] = s1;
}

// ---------------- GEMM1 (HMMA): h1 = x @ W1 ----------------------------------
// 128x64 tile per 256-thread block; warp = 32 rows x 32 cols.
// bf16 3-pass split: h1 = Ahi*Bhi + Ahi*Blo + Alo*Bhi (fp32 accum).
#define KC   64             // K chunk (floats)
#define ROWU 36             // u32 per smem row (32 data + 4 pad)
#define SA   (128 * ROWU)
#define SB   (64 * ROWU)
#define SM_AHI 0
#define SM_ALO SA
#define SM_BHI (2 * SA)
#define SM_BLO (2 * SA + SB)
#define SMEM_U32 (2 * SA + 2 * SB)
#define SMEM_BYTES (SMEM_U32 * 4)

__device__ __forceinline__ void mma_bf16(float& d0, float& d1, float& d2, float& d3,
                                         uint32_t a0, uint32_t a1, uint32_t a2, uint32_t a3,
                                         uint32_t b0, uint32_t b1) {
    asm volatile(
        "mma.sync.aligned.m16n8k16.row.col.f32.bf16.bf16.f32 "
        "{%0,%1,%2,%3}, {%4,%5,%6,%7}, {%8,%9}, {%0,%1,%2,%3};"
        : "+f"(d0), "+f"(d1), "+f"(d2), "+f"(d3)
        : "r"(a0), "r"(a1), "r"(a2), "r"(a3), "r"(b0), "r"(b1));
}

__global__ void __launch_bounds__(256, 2) k_gemm1(const float* __restrict__ x) {
    extern __shared__ __align__(16) uint32_t sm[];
    int t = threadIdx.x;
    int wid = t >> 5;
    int lane = t & 31;
    int g   = lane >> 2;
    int tig = lane & 3;
    int row0 = blockIdx.x * 128;
    int mrow0 = (wid >> 1) * 32;
    int ncol0 = (wid & 1) * 32;

    float acc[2][4][4];
#pragma unroll
    for (int mt = 0; mt < 2; ++mt)
#pragma unroll
        for (int nt = 0; nt < 4; ++nt)
#pragma unroll
            for (int i = 0; i < 4; ++i) acc[mt][nt][i] = 0.f;

    const uint32_t* wh = (const uint32_t*)g_w1t_hi;
    const uint32_t* wl = (const uint32_t*)g_w1t_lo;

    for (int k0 = 0; k0 < FF; k0 += KC) {
#pragma unroll
        for (int i = 0; i < 8; ++i) {
            int idx = t + i * 256;
            int row = idx >> 4;
            int c4  = (idx & 15) << 2;
            int gr  = row0 + row;
            float4 v = (gr < NN) ? *(const float4*)&x[(size_t)gr * FF + k0 + c4]
                                 : make_float4(0.f, 0.f, 0.f, 0.f);
            __nv_bfloat162 h01 = __floats2bfloat162_rn(v.x, v.y);
            __nv_bfloat162 h23 = __floats2bfloat162_rn(v.z, v.w);
            __nv_bfloat162 l01 = __floats2bfloat162_rn(v.x - __bfloat162float(__low2bfloat16(h01)),
                                                       v.y - __bfloat162float(__high2bfloat16(h01)));
            __nv_bfloat162 l23 = __floats2bfloat162_rn(v.z - __bfloat162float(__low2bfloat16(h23)),
                                                       v.w - __bfloat162float(__high2bfloat16(h23)));
            int base = row * ROWU + (c4 >> 1);
            sm[SM_AHI + base]     = *(uint32_t*)&h01;
            sm[SM_AHI + base + 1] = *(uint32_t*)&h23;
            sm[SM_ALO + base]     = *(uint32_t*)&l01;
            sm[SM_ALO + base + 1] = *(uint32_t*)&l23;
        }
#pragma unroll
        for (int i = 0; i < 8; ++i) {
            int idx = t + i * 256;
            int row = idx >> 5;
            int cp  = idx & 31;
            sm[SM_BHI + row * ROWU + cp] = wh[row * 128 + (k0 >> 1) + cp];
            sm[SM_BLO + row * ROWU + cp] = wl[row * 128 + (k0 >> 1) + cp];
        }
        __syncthreads();

#pragma unroll
        for (int ks = 0; ks < 4; ++ks) {
            int kb = ks * 8;
            uint32_t ahi[2][4], alo[2][4];
#pragma unroll
            for (int mt = 0; mt < 2; ++mt) {
                int r = mrow0 + mt * 16 + g;
                int b0 = r * ROWU + kb + tig;
                int b1 = (r + 8) * ROWU + kb + tig;
                ahi[mt][0] = sm[SM_AHI + b0];
                ahi[mt][1] = sm[SM_AHI + b1];
                ahi[mt][2] = sm[SM_AHI + b0 + 4];
                ahi[mt][3] = sm[SM_AHI + b1 + 4];
                alo[mt][0] = sm[SM_ALO + b0];
                alo[mt][1] = sm[SM_ALO + b1];
                alo[mt][2] = sm[SM_ALO + b0 + 4];
                alo[mt][3] = sm[SM_ALO + b1 + 4];
            }
#pragma unroll
            for (int nt = 0; nt < 4; ++nt) {
                int n = ncol0 + nt * 8 + g;
                int bo = n * ROWU + kb + tig;
                uint32_t bhi0 = sm[SM_BHI + bo], bhi1 = sm[SM_BHI + bo + 4];
                uint32_t blo0 = sm[SM_BLO + bo], blo1 = sm[SM_BLO + bo + 4];
#pragma unroll
                for (int mt = 0; mt < 2; ++mt) {
                    float* a = acc[mt][nt];
                    mma_bf16(a[0], a[1], a[2], a[3],
                             ahi[mt][0], ahi[mt][1], ahi[mt][2], ahi[mt][3], bhi0, bhi1);
                    mma_bf16(a[0], a[1], a[2], a[3],
                             ahi[mt][0], ahi[mt][1], ahi[mt][2], ahi[mt][3], blo0, blo1);
                    mma_bf16(a[0], a[1], a[2], a[3],
                             alo[mt][0], alo[mt][1], alo[mt][2], alo[mt][3], bhi0, bhi1);
                }
            }
        }
        __syncthreads();
    }

#pragma unroll
    for (int mt = 0; mt < 2; ++mt) {
#pragma unroll
        for (int nt = 0; nt < 4; ++nt) {
            int r = row0 + mrow0 + mt * 16 + g;
            int c = ncol0 + nt * 8 + tig * 2;
            float* a = acc[mt][nt];
            if (r < NN)     *(float2*)&g_h1[(size_t)r * HH + c]       = make_float2(a[0], a[1]);
            if (r + 8 < NN) *(float2*)&g_h1[(size_t)(r + 8) * HH + c] = make_float2(a[2], a[3]);
        }
    }
}

// ---------------- agg1: x2 = relu( dinv*(sum dinv[s]*h1[s] + dinv*h1[n]) + b1 )
// 2 nodes per warp: half-warp (16 lanes) per node, lane handles 4 dims (float4).
__global__ void k_agg1(const float* __restrict__ b1) {
    int warp = (blockIdx.x * blockDim.x + threadIdx.x) >> 5;
    int lane = threadIdx.x & 31;
    int half = lane >> 4;
    int hl   = lane & 15;
    int n = warp * 2 + half;
    if (n >= NN) return;

    const float4* h1 = (const float4*)g_h1;

    float di = g_dinv[n];
    float4 hv = h1[(size_t)n * 16 + hl];
    // acc accumulates sum dinv[s]*h[s] + di*h[n]; final x2 = relu(di*acc + b1)
    float4 acc = make_float4(di * hv.x, di * hv.y, di * hv.z, di * hv.w);

    int e  = g_start[n];
    int eE = g_start[n + 1];
#pragma unroll 4
    for (; e < eE; ++e) {
        int   s  = __ldg(&g_csr[e]);
        float ds = __ldg(&g_dinv[s]);
        float4 v = h1[(size_t)s * 16 + hl];
        acc.x += ds * v.x;  acc.y += ds * v.y;
        acc.z += ds * v.z;  acc.w += ds * v.w;
    }
    float4 bb = ((const float4*)b1)[hl];
    acc.x = fmaxf(di * acc.x + bb.x, 0.f);
    acc.y = fmaxf(di * acc.y + bb.y, 0.f);
    acc.z = fmaxf(di * acc.z + bb.z, 0.f);
    acc.w = fmaxf(di * acc.w + bb.w, 0.f);
    ((float4*)g_x2)[(size_t)n * 16 + hl] = acc;
}

// ---------------- GEMM2: z' = dinv * (x2 @ W2)  (100000x64 @ 64x16) ---------
__global__ void k_gemm2(const float* __restrict__ W2) {
    __shared__ float Xs[64][65];
    __shared__ float Ws[64][16];
    int t = threadIdx.x;
    int n0 = blockIdx.x * 64;
    int r  = t >> 2;
    int c0 = (t & 3) << 2;

#pragma unroll
    for (int it = 0; it < 16; ++it) {
        int fid = t + it * 256;
        int rr = fid >> 6;
        int k  = fid & 63;
        int gn = n0 + rr;
        Xs[rr][k] = (gn < NN) ? g_x2[(size_t)gn * HH + k] : 0.f;
    }
    {
        int k = t >> 2;
        int c = (t & 3) << 2;
        *(float4*)&Ws[k][c] = *(const float4*)&W2[(size_t)k * CC + c];
    }
    __syncthreads();

    float acc0 = 0.f, acc1 = 0.f, acc2 = 0.f, acc3 = 0.f;
#pragma unroll
    for (int k = 0; k < 64; ++k) {
        float a = Xs[r][k];
        float4 b = *(const float4*)&Ws[k][c0];
        acc0 += a * b.x; acc1 += a * b.y; acc2 += a * b.z; acc3 += a * b.w;
    }
    int gn = n0 + r;
    if (gn < NN) {
        float di = g_dinv[gn];
        *(float4*)&g_z[(size_t)gn * CC + c0] =
            make_float4(di * acc0, di * acc1, di * acc2, di * acc3);
    }
}

// ---------------- agg2 + bias + log_softmax ---------------------------------
// z is prescaled (z' = dinv*z): out_pre = di*(sum z'[s] + z'[n]) + b2.
// 2 nodes per warp: half-warp per node, lane handles 1 of 16 dims.
__global__ void k_agg2(const float* __restrict__ b2, float* __restrict__ out) {
    int warp = (blockIdx.x * blockDim.x + threadIdx.x) >> 5;
    int lane = threadIdx.x & 31;
    int half = lane >> 4;
    int c    = lane & 15;
    int n = warp * 2 + half;
    if (n >= NN) return;

    float di = g_dinv[n];
    float acc = g_z[(size_t)n * CC + c];   // z'[n] = di*z[n] (self term)

    int e  = g_start[n];
    int eE = g_start[n + 1];
#pragma unroll 4
    for (; e < eE; ++e) {
        int s = __ldg(&g_csr[e]);
        acc += g_z[(size_t)s * CC + c];
    }
    acc = di * acc + b2[c];

    // log_softmax over 16 dims within the half-warp
    float m = acc;
#pragma unroll
    for (int o = 8; o >= 1; o >>= 1)
        m = fmaxf(m, __shfl_xor_sync(0xffffffffu, m, o, 16));
    float ex = expf(acc - m);
    float s = ex;
#pragma unroll
    for (int o = 8; o >= 1; o >>= 1)
        s += __shfl_xor_sync(0xffffffffu, s, o, 16);
    out[(size_t)n * CC + c] = acc - m - logf(s);
}

// ---------------- launch -----------------------------------------------------
// Side stream: edge chain.  Main: wsplit+gemm1 (gemm1 = 4th call -> profiled).
extern "C" void kernel_launch(void* const* d_in, const int* in_sizes, int n_in,
                              void* d_out, int out_size) {
    const float* x  = (const float*)d_in[0];
    const void*  ei = d_in[1];
    const float* W1 = (const float*)d_in[2];
    const float* b1 = (const float*)d_in[3];
    const float* W2 = (const float*)d_in[4];
    const float* b2 = (const float*)d_in[5];
    float* out = (float*)d_out;

    cudaFuncSetAttribute(k_gemm1, cudaFuncAttributeMaxDynamicSharedMemorySize, SMEM_BYTES);

    cudaStream_t side;
    cudaEvent_t evFork, evJoin;
    cudaStreamCreateWithFlags(&side, cudaStreamNonBlocking);
    cudaEventCreateWithFlags(&evFork, cudaEventDisableTiming);
    cudaEventCreateWithFlags(&evJoin, cudaEventDisableTiming);

    cudaEventRecord(evFork, cudaStreamPerThread);
    cudaStreamWaitEvent(side, evFork, 0);

    k_zero   <<<(NN + 255) / 256, 256, 0, side>>>((const int*)ei);      // 0
    k_hist   <<<(EE / 2 + 255) / 256, 256, 0, side>>>(ei);              // 1
    k_wsplit <<<(HH * FF + 255) / 256, 256>>>(W1);                      // 2 (main)
    k_gemm1  <<<(NN + 127) / 128, 256, SMEM_BYTES>>>(x);                // 3 (main) <- profiled
    k_scan1  <<<NB1, 1024, 0, side>>>();                                // 4
    k_scan23 <<<NB1, 1024, 0, side>>>();                                // 5
    k_scatter<<<(EE / 2 + 255) / 256, 256, 0, side>>>(ei);              // 6
    cudaEventRecord(evJoin, side);

    cudaStreamWaitEvent(cudaStreamPerThread, evJoin, 0);
    k_agg1  <<<(NN / 2 + 255) / 256 * 32, 256>>>(b1);                   // 7
    k_gemm2 <<<(NN + 63) / 64, 256>>>(W2);                              // 8
    k_agg2  <<<(NN / 2 + 255) / 256 * 32, 256>>>(b2, out);              // 9
}

// round 8
// speedup vs baseline: 1.6099x; 1.0433x over previous
#include <cuda_runtime.h>
#include <cuda_bf16.h>
#include <cstdint>

// GCN: out = log_softmax( agg( relu( agg(x@W1) + b1 ) @ W2 ) + b2 )
// agg uses symmetric D^-1/2 (A+I) D^-1/2 with in-degree (dst) + self loops.
// Norm factored: agg(h)[d] = dinv[d] * ( sum_{s in N(d)} dinv[s]*h[s] + dinv[d]*h[d] )
// CSR stores src only (4B/edge); layer-2 GEMV (x2@W2) fused into agg1 epilogue,
// output prescaled: z' = dinv * (x2 @ W2).

#define NN 100000
#define EE 1600000
#define FF 256
#define HH 64
#define CC 16
#define NB1 98           // ceil(NN/1024)

// ---------------- scratch (static device globals; no allocation) -------------
__device__ int   g_deg[NN];
__device__ int   g_start[NN + 1];
__device__ int   g_cursor[NN];
__device__ float g_dinv[NN];
__device__ int   g_csr[EE];              // src node only
__device__ float g_h1[(size_t)NN * HH];  // x @ W1
__device__ float g_z [(size_t)NN * CC];  // dinv * (relu(agg1+b1) @ W2)
__device__ int   g_bsum[128];
__device__ int   g_is64;                 // edge_index stored as int64 (vs int32)
__device__ __nv_bfloat16 g_w1t_hi[HH * FF];  // W1^T split, [64][256] bf16 (k-contig)
__device__ __nv_bfloat16 g_w1t_lo[HH * FF];

// ---------------- W1^T bf16 split prep ---------------------------------------
__global__ void k_wsplit(const float* __restrict__ W1) {
    int idx = blockIdx.x * blockDim.x + threadIdx.x;   // over [64][256]
    if (idx >= HH * FF) return;
    int c = idx >> 8;       // out col  (0..63)
    int k = idx & 255;      // k        (0..255)
    float v = W1[(size_t)k * HH + c];
    __nv_bfloat16 hi = __float2bfloat16(v);
    __nv_bfloat16 lo = __float2bfloat16(v - __bfloat162float(hi));
    g_w1t_hi[c * FF + k] = hi;
    g_w1t_lo[c * FF + k] = lo;
}

// ---------------- zero + dtype detect ----------------------------------------
__global__ void k_zero(const int* __restrict__ ei32) {
    int i = blockIdx.x * blockDim.x + threadIdx.x;
    if (i < NN) g_deg[i] = 0;
    if (blockIdx.x == 0 && threadIdx.x == 0) {
        int s = 0;
        // int64 little-endian: odd 32-bit words are 0 (values < 2^17)
        for (int j = 0; j < 64; ++j) s |= ei32[2 * j + 1];
        g_is64 = (s == 0) ? 1 : 0;
    }
}

// 2 edges per thread, 16B/8B vector loads of the dst row
__global__ void k_hist(const void* __restrict__ ei) {
    int i = blockIdx.x * blockDim.x + threadIdx.x;   // pair index
    if (i >= EE / 2) return;
    int d0, d1;
    if (g_is64) {
        longlong2 p = ((const longlong2*)((const long long*)ei + EE))[i];
        d0 = (int)p.x; d1 = (int)p.y;
    } else {
        int2 p = ((const int2*)((const int*)ei + EE))[i];
        d0 = p.x; d1 = p.y;
    }
    atomicAdd(&g_deg[d0], 1);
    atomicAdd(&g_deg[d1], 1);
}

// ---------------- scan (with fused dinv) -------------------------------------
__global__ void k_scan1() {
    __shared__ int s[1024];
    int t = threadIdx.x;
    int i = blockIdx.x * 1024 + t;
    int v = (i < NN) ? g_deg[i] : 0;
    if (i < NN) g_dinv[i] = rsqrtf((float)(v + 1));   // +1 self loop
    s[t] = v;
    __syncthreads();
    for (int off = 1; off < 1024; off <<= 1) {
        int add = (t >= off) ? s[t - off] : 0;
        __syncthreads();
        s[t] += add;
        __syncthreads();
    }
    if (i < NN) g_start[i] = s[t] - v;        // exclusive within block
    if (t == 1023) g_bsum[blockIdx.x] = s[t]; // block total
}

// fused scan2+scan3: each block sums bsum[0..b) itself (L2-hot, tiny)
__global__ void k_scan23() {
    __shared__ int pref;
    int b = blockIdx.x;
    int t = threadIdx.x;
    if (t == 0) {
        int run = 0;
#pragma unroll 4
        for (int j = 0; j < b; ++j) run += g_bsum[j];
        pref = run;
        if (b == 0) g_start[NN] = EE;
    }
    __syncthreads();
    int i = b * 1024 + t;
    if (i < NN) {
        int v = g_start[i] + pref;
        g_start[i]  = v;
        g_cursor[i] = v;
    }
}

// 2 edges per thread; no dinv gathers, 4B csr writes
__global__ void k_scatter(const void* __restrict__ ei) {
    int i = blockIdx.x * blockDim.x + threadIdx.x;   // pair index
    if (i >= EE / 2) return;
    int s0, s1, d0, d1;
    if (g_is64) {
        longlong2 sp = ((const longlong2*)ei)[i];
        longlong2 dp = ((const longlong2*)((const long long*)ei + EE))[i];
        s0 = (int)sp.x; s1 = (int)sp.y; d0 = (int)dp.x; d1 = (int)dp.y;
    } else {
        int2 sp = ((const int2*)ei)[i];
        int2 dp = ((const int2*)((const int*)ei + EE))[i];
        s0 = sp.x; s1 = sp.y; d0 = dp.x; d1 = dp.y;
    }
    int p0 = atomicAdd(&g_cursor[d0], 1);
    g_csr[p0] = s0;
    int p1 = atomicAdd(&g_cursor[d1], 1);
    g_csr[p1] = s1;
}

// ---------------- GEMM1 (HMMA): h1 = x @ W1 ----------------------------------
// 128x64 tile per 256-thread block; warp = 32 rows x 32 cols.
// bf16 3-pass split: h1 = Ahi*Bhi + Ahi*Blo + Alo*Bhi (fp32 accum).
#define KC   64             // K chunk (floats)
#define ROWU 36             // u32 per smem row (32 data + 4 pad)
#define SA   (128 * ROWU)
#define SB   (64 * ROWU)
#define SM_AHI 0
#define SM_ALO SA
#define SM_BHI (2 * SA)
#define SM_BLO (2 * SA + SB)
#define SMEM_U32 (2 * SA + 2 * SB)
#define SMEM_BYTES (SMEM_U32 * 4)

__device__ __forceinline__ void mma_bf16(float& d0, float& d1, float& d2, float& d3,
                                         uint32_t a0, uint32_t a1, uint32_t a2, uint32_t a3,
                                         uint32_t b0, uint32_t b1) {
    asm volatile(
        "mma.sync.aligned.m16n8k16.row.col.f32.bf16.bf16.f32 "
        "{%0,%1,%2,%3}, {%4,%5,%6,%7}, {%8,%9}, {%0,%1,%2,%3};"
        : "+f"(d0), "+f"(d1), "+f"(d2), "+f"(d3)
        : "r"(a0), "r"(a1), "r"(a2), "r"(a3), "r"(b0), "r"(b1));
}

__global__ void __launch_bounds__(256, 2) k_gemm1(const float* __restrict__ x) {
    extern __shared__ __align__(16) uint32_t sm[];
    int t = threadIdx.x;
    int wid = t >> 5;
    int lane = t & 31;
    int g   = lane >> 2;
    int tig = lane & 3;
    int row0 = blockIdx.x * 128;
    int mrow0 = (wid >> 1) * 32;
    int ncol0 = (wid & 1) * 32;

    float acc[2][4][4];
#pragma unroll
    for (int mt = 0; mt < 2; ++mt)
#pragma unroll
        for (int nt = 0; nt < 4; ++nt)
#pragma unroll
            for (int i = 0; i < 4; ++i) acc[mt][nt][i] = 0.f;

    const uint32_t* wh = (const uint32_t*)g_w1t_hi;
    const uint32_t* wl = (const uint32_t*)g_w1t_lo;

    for (int k0 = 0; k0 < FF; k0 += KC) {
#pragma unroll
        for (int i = 0; i < 8; ++i) {
            int idx = t + i * 256;
            int row = idx >> 4;
            int c4  = (idx & 15) << 2;
            int gr  = row0 + row;
            float4 v = (gr < NN) ? *(const float4*)&x[(size_t)gr * FF + k0 + c4]
                                 : make_float4(0.f, 0.f, 0.f, 0.f);
            __nv_bfloat162 h01 = __floats2bfloat162_rn(v.x, v.y);
            __nv_bfloat162 h23 = __floats2bfloat162_rn(v.z, v.w);
            __nv_bfloat162 l01 = __floats2bfloat162_rn(v.x - __bfloat162float(__low2bfloat16(h01)),
                                                       v.y - __bfloat162float(__high2bfloat16(h01)));
            __nv_bfloat162 l23 = __floats2bfloat162_rn(v.z - __bfloat162float(__low2bfloat16(h23)),
                                                       v.w - __bfloat162float(__high2bfloat16(h23)));
            int base = row * ROWU + (c4 >> 1);
            sm[SM_AHI + base]     = *(uint32_t*)&h01;
            sm[SM_AHI + base + 1] = *(uint32_t*)&h23;
            sm[SM_ALO + base]     = *(uint32_t*)&l01;
            sm[SM_ALO + base + 1] = *(uint32_t*)&l23;
        }
#pragma unroll
        for (int i = 0; i < 8; ++i) {
            int idx = t + i * 256;
            int row = idx >> 5;
            int cp  = idx & 31;
            sm[SM_BHI + row * ROWU + cp] = wh[row * 128 + (k0 >> 1) + cp];
            sm[SM_BLO + row * ROWU + cp] = wl[row * 128 + (k0 >> 1) + cp];
        }
        __syncthreads();

#pragma unroll
        for (int ks = 0; ks < 4; ++ks) {
            int kb = ks * 8;
            uint32_t ahi[2][4], alo[2][4];
#pragma unroll
            for (int mt = 0; mt < 2; ++mt) {
                int r = mrow0 + mt * 16 + g;
                int b0 = r * ROWU + kb + tig;
                int b1 = (r + 8) * ROWU + kb + tig;
                ahi[mt][0] = sm[SM_AHI + b0];
                ahi[mt][1] = sm[SM_AHI + b1];
                ahi[mt][2] = sm[SM_AHI + b0 + 4];
                ahi[mt][3] = sm[SM_AHI + b1 + 4];
                alo[mt][0] = sm[SM_ALO + b0];
                alo[mt][1] = sm[SM_ALO + b1];
                alo[mt][2] = sm[SM_ALO + b0 + 4];
                alo[mt][3] = sm[SM_ALO + b1 + 4];
            }
#pragma unroll
            for (int nt = 0; nt < 4; ++nt) {
                int n = ncol0 + nt * 8 + g;
                int bo = n * ROWU + kb + tig;
                uint32_t bhi0 = sm[SM_BHI + bo], bhi1 = sm[SM_BHI + bo + 4];
                uint32_t blo0 = sm[SM_BLO + bo], blo1 = sm[SM_BLO + bo + 4];
#pragma unroll
                for (int mt = 0; mt < 2; ++mt) {
                    float* a = acc[mt][nt];
                    mma_bf16(a[0], a[1], a[2], a[3],
                             ahi[mt][0], ahi[mt][1], ahi[mt][2], ahi[mt][3], bhi0, bhi1);
                    mma_bf16(a[0], a[1], a[2], a[3],
                             ahi[mt][0], ahi[mt][1], ahi[mt][2], ahi[mt][3], blo0, blo1);
                    mma_bf16(a[0], a[1], a[2], a[3],
                             alo[mt][0], alo[mt][1], alo[mt][2], alo[mt][3], bhi0, bhi1);
                }
            }
        }
        __syncthreads();
    }

#pragma unroll
    for (int mt = 0; mt < 2; ++mt) {
#pragma unroll
        for (int nt = 0; nt < 4; ++nt) {
            int r = row0 + mrow0 + mt * 16 + g;
            int c = ncol0 + nt * 8 + tig * 2;
            float* a = acc[mt][nt];
            if (r < NN)     *(float2*)&g_h1[(size_t)r * HH + c]       = make_float2(a[0], a[1]);
            if (r + 8 < NN) *(float2*)&g_h1[(size_t)(r + 8) * HH + c] = make_float2(a[2], a[3]);
        }
    }
}

// ---------------- agg1 + fused GEMV (x2@W2, prescaled) -----------------------
// 2 nodes per warp: half-warp per node, lane handles 4 dims (float4).
// Epilogue: x2 row (64 dims across 16 lanes) -> z[16] via in-warp GEMV:
//   each lane: 16 partials from its 4 k-dims; vector-halving butterfly leaves
//   lane hl holding z[hl]; store z' = dinv * z.
__global__ void __launch_bounds__(256) k_agg1(const float* __restrict__ b1,
                                              const float* __restrict__ W2) {
    __shared__ float Ws[HH][CC + 1];     // pad 17 -> 2-way conflicts max
    {
        int t = threadIdx.x;
        if (t < 256) {
#pragma unroll
            for (int i = t; i < HH * CC; i += 256)
                Ws[i >> 4][i & 15] = W2[i];
        }
    }
    __syncthreads();

    int warp = (blockIdx.x * blockDim.x + threadIdx.x) >> 5;
    int lane = threadIdx.x & 31;
    int half = lane >> 4;
    int hl   = lane & 15;
    int n = warp * 2 + half;
    if (n >= NN) return;

    const float4* h1 = (const float4*)g_h1;

    float di = g_dinv[n];
    float4 hv = h1[(size_t)n * 16 + hl];
    // acc = sum dinv[s]*h[s] + di*h[n]; x2 = relu(di*acc + b1)
    float4 acc = make_float4(di * hv.x, di * hv.y, di * hv.z, di * hv.w);

    int e  = g_start[n];
    int eE = g_start[n + 1];
#pragma unroll 4
    for (; e < eE; ++e) {
        int   s  = __ldg(&g_csr[e]);
        float ds = __ldg(&g_dinv[s]);
        float4 v = h1[(size_t)s * 16 + hl];
        acc.x += ds * v.x;  acc.y += ds * v.y;
        acc.z += ds * v.z;  acc.w += ds * v.w;
    }
    float4 bb = ((const float4*)b1)[hl];
    float x2v[4];
    x2v[0] = fmaxf(di * acc.x + bb.x, 0.f);
    x2v[1] = fmaxf(di * acc.y + bb.y, 0.f);
    x2v[2] = fmaxf(di * acc.z + bb.z, 0.f);
    x2v[3] = fmaxf(di * acc.w + bb.w, 0.f);

    // ---- fused GEMV: p[c] = sum_j x2v[j] * W2[4*hl+j][c] ----
    float p[16];
#pragma unroll
    for (int c = 0; c < 16; ++c) p[c] = 0.f;
#pragma unroll
    for (int j = 0; j < 4; ++j) {
        float xv = x2v[j];
        int row = hl * 4 + j;
#pragma unroll
        for (int c = 0; c < 16; ++c)
            p[c] += xv * Ws[row][c];
    }
    // ---- butterfly reduce across 16 lanes (vector halving) ----
#pragma unroll
    for (int o = 8; o >= 1; o >>= 1) {
        bool up = (hl & o) != 0;
#pragma unroll
        for (int i = 0; i < 8; ++i) {
            if (i < o) {
                float send = up ? p[i] : p[o + i];
                float other = __shfl_xor_sync(0xffffffffu, send, o, 16);
                p[i] = (up ? p[o + i] : p[i]) + other;
            }
        }
    }
    // lane hl holds z[hl]; prescale and store
    g_z[(size_t)n * CC + hl] = di * p[0];
}

// ---------------- agg2 + bias + log_softmax ---------------------------------
// z is prescaled (z' = dinv*z): out_pre = di*(sum z'[s] + z'[n]) + b2.
// 2 nodes per warp: half-warp per node, lane handles 1 of 16 dims.
__global__ void k_agg2(const float* __restrict__ b2, float* __restrict__ out) {
    int warp = (blockIdx.x * blockDim.x + threadIdx.x) >> 5;
    int lane = threadIdx.x & 31;
    int half = lane >> 4;
    int c    = lane & 15;
    int n = warp * 2 + half;
    if (n >= NN) return;

    float di = g_dinv[n];
    float acc = g_z[(size_t)n * CC + c];   // self term (already prescaled)

    int e  = g_start[n];
    int eE = g_start[n + 1];
#pragma unroll 4
    for (; e < eE; ++e) {
        int s = __ldg(&g_csr[e]);
        acc += g_z[(size_t)s * CC + c];
    }
    acc = di * acc + b2[c];

    // log_softmax over 16 dims within the half-warp
    float m = acc;
#pragma unroll
    for (int o = 8; o >= 1; o >>= 1)
        m = fmaxf(m, __shfl_xor_sync(0xffffffffu, m, o, 16));
    float ex = expf(acc - m);
    float s = ex;
#pragma unroll
    for (int o = 8; o >= 1; o >>= 1)
        s += __shfl_xor_sync(0xffffffffu, s, o, 16);
    out[(size_t)n * CC + c] = acc - m - logf(s);
}

// ---------------- launch -----------------------------------------------------
// Side stream: edge chain.  Main: wsplit+gemm1 (gemm1 = 4th call -> profiled).
extern "C" void kernel_launch(void* const* d_in, const int* in_sizes, int n_in,
                              void* d_out, int out_size) {
    const float* x  = (const float*)d_in[0];
    const void*  ei = d_in[1];
    const float* W1 = (const float*)d_in[2];
    const float* b1 = (const float*)d_in[3];
    const float* W2 = (const float*)d_in[4];
    const float* b2 = (const float*)d_in[5];
    float* out = (float*)d_out;

    cudaFuncSetAttribute(k_gemm1, cudaFuncAttributeMaxDynamicSharedMemorySize, SMEM_BYTES);

    cudaStream_t side;
    cudaEvent_t evFork, evJoin;
    cudaStreamCreateWithFlags(&side, cudaStreamNonBlocking);
    cudaEventCreateWithFlags(&evFork, cudaEventDisableTiming);
    cudaEventCreateWithFlags(&evJoin, cudaEventDisableTiming);

    cudaEventRecord(evFork, cudaStreamPerThread);
    cudaStreamWaitEvent(side, evFork, 0);

    k_zero   <<<(NN + 255) / 256, 256, 0, side>>>((const int*)ei);      // 0
    k_hist   <<<(EE / 2 + 255) / 256, 256, 0, side>>>(ei);              // 1
    k_wsplit <<<(HH * FF + 255) / 256, 256>>>(W1);                      // 2 (main)
    k_gemm1  <<<(NN + 127) / 128, 256, SMEM_BYTES>>>(x);                // 3 (main) <- profiled
    k_scan1  <<<NB1, 1024, 0, side>>>();                                // 4
    k_scan23 <<<NB1, 1024, 0, side>>>();                                // 5
    k_scatter<<<(EE / 2 + 255) / 256, 256, 0, side>>>(ei);              // 6
    cudaEventRecord(evJoin, side);

    cudaStreamWaitEvent(cudaStreamPerThread, evJoin, 0);
    k_agg1  <<<(NN / 2 + 255) / 256 * 32, 256>>>(b1, W2);               // 7
    k_agg2  <<<(NN / 2 + 255) / 256 * 32, 256>>>(b2, out);              // 8
}

// round 9
// speedup vs baseline: 1.7418x; 1.0819x over previous
#include <cuda_runtime.h>
#include <cuda_bf16.h>
#include <cuda_fp16.h>
#include <cstdint>

// GCN: out = log_softmax( agg( relu( agg(x@W1) + b1 ) @ W2 ) + b2 )
// agg uses symmetric D^-1/2 (A+I) D^-1/2 with in-degree (dst) + self loops.
// Norm factored: agg(h)[d] = dinv[d] * ( sum_{s in N(d)} dinv[s]*h[s] + dinv[d]*h[d] )
// CSR stores src only (4B/edge).  h1 stored fp16 (halves agg1 gather bytes).
// Layer-2 GEMV (x2@W2) fused into agg1 epilogue; z' = dinv * (x2@W2).

#define NN 100000
#define EE 1600000
#define FF 256
#define HH 64
#define CC 16
#define NB1 98           // ceil(NN/1024)

// ---------------- scratch (static device globals; no allocation) -------------
__device__ int    g_deg[NN];
__device__ int    g_start[NN + 1];
__device__ int    g_cursor[NN];
__device__ float  g_dinv[NN];
__device__ int    g_csr[EE];              // src node only
__device__ __half g_h1[(size_t)NN * HH];  // x @ W1  (fp16, 128B/row)
__device__ float  g_z [(size_t)NN * CC];  // dinv * (relu(agg1+b1) @ W2)
__device__ int    g_bsum[128];
__device__ int    g_is64;                 // edge_index stored as int64 (vs int32)
__device__ __nv_bfloat16 g_w1t_hi[HH * FF];  // W1^T split, [64][256] bf16 (k-contig)
__device__ __nv_bfloat16 g_w1t_lo[HH * FF];

// ---------------- W1^T bf16 split prep ---------------------------------------
__global__ void k_wsplit(const float* __restrict__ W1) {
    int idx = blockIdx.x * blockDim.x + threadIdx.x;   // over [64][256]
    if (idx >= HH * FF) return;
    int c = idx >> 8;       // out col  (0..63)
    int k = idx & 255;      // k        (0..255)
    float v = W1[(size_t)k * HH + c];
    __nv_bfloat16 hi = __float2bfloat16(v);
    __nv_bfloat16 lo = __float2bfloat16(v - __bfloat162float(hi));
    g_w1t_hi[c * FF + k] = hi;
    g_w1t_lo[c * FF + k] = lo;
}

// ---------------- zero + dtype detect ----------------------------------------
__global__ void k_zero(const int* __restrict__ ei32) {
    int i = blockIdx.x * blockDim.x + threadIdx.x;
    if (i < NN) g_deg[i] = 0;
    if (blockIdx.x == 0 && threadIdx.x == 0) {
        int s = 0;
        // int64 little-endian: odd 32-bit words are 0 (values < 2^17)
        for (int j = 0; j < 64; ++j) s |= ei32[2 * j + 1];
        g_is64 = (s == 0) ? 1 : 0;
    }
}

// 2 edges per thread, 16B/8B vector loads of the dst row
__global__ void k_hist(const void* __restrict__ ei) {
    int i = blockIdx.x * blockDim.x + threadIdx.x;   // pair index
    if (i >= EE / 2) return;
    int d0, d1;
    if (g_is64) {
        longlong2 p = ((const longlong2*)((const long long*)ei + EE))[i];
        d0 = (int)p.x; d1 = (int)p.y;
    } else {
        int2 p = ((const int2*)((const int*)ei + EE))[i];
        d0 = p.x; d1 = p.y;
    }
    atomicAdd(&g_deg[d0], 1);
    atomicAdd(&g_deg[d1], 1);
}

// ---------------- scan (with fused dinv) -------------------------------------
__global__ void k_scan1() {
    __shared__ int s[1024];
    int t = threadIdx.x;
    int i = blockIdx.x * 1024 + t;
    int v = (i < NN) ? g_deg[i] : 0;
    if (i < NN) g_dinv[i] = rsqrtf((float)(v + 1));   // +1 self loop
    s[t] = v;
    __syncthreads();
    for (int off = 1; off < 1024; off <<= 1) {
        int add = (t >= off) ? s[t - off] : 0;
        __syncthreads();
        s[t] += add;
        __syncthreads();
    }
    if (i < NN) g_start[i] = s[t] - v;        // exclusive within block
    if (t == 1023) g_bsum[blockIdx.x] = s[t]; // block total
}

// fused scan2+scan3: each block sums bsum[0..b) itself (L2-hot, tiny)
__global__ void k_scan23() {
    __shared__ int pref;
    int b = blockIdx.x;
    int t = threadIdx.x;
    if (t == 0) {
        int run = 0;
#pragma unroll 4
        for (int j = 0; j < b; ++j) run += g_bsum[j];
        pref = run;
        if (b == 0) g_start[NN] = EE;
    }
    __syncthreads();
    int i = b * 1024 + t;
    if (i < NN) {
        int v = g_start[i] + pref;
        g_start[i]  = v;
        g_cursor[i] = v;
    }
}

// 2 edges per thread; no dinv gathers, 4B csr writes
__global__ void k_scatter(const void* __restrict__ ei) {
    int i = blockIdx.x * blockDim.x + threadIdx.x;   // pair index
    if (i >= EE / 2) return;
    int s0, s1, d0, d1;
    if (g_is64) {
        longlong2 sp = ((const longlong2*)ei)[i];
        longlong2 dp = ((const longlong2*)((const long long*)ei + EE))[i];
        s0 = (int)sp.x; s1 = (int)sp.y; d0 = (int)dp.x; d1 = (int)dp.y;
    } else {
        int2 sp = ((const int2*)ei)[i];
        int2 dp = ((const int2*)((const int*)ei + EE))[i];
        s0 = sp.x; s1 = sp.y; d0 = dp.x; d1 = dp.y;
    }
    int p0 = atomicAdd(&g_cursor[d0], 1);
    g_csr[p0] = s0;
    int p1 = atomicAdd(&g_cursor[d1], 1);
    g_csr[p1] = s1;
}

// ---------------- GEMM1 (HMMA): h1 = x @ W1 (fp16 out) -----------------------
// 128x64 tile per 256-thread block; warp = 32 rows x 32 cols.
// bf16 3-pass split: h1 = Ahi*Bhi + Ahi*Blo + Alo*Bhi (fp32 accum).
#define KC   64             // K chunk (floats)
#define ROWU 36             // u32 per smem row (32 data + 4 pad)
#define SA   (128 * ROWU)
#define SB   (64 * ROWU)
#define SM_AHI 0
#define SM_ALO SA
#define SM_BHI (2 * SA)
#define SM_BLO (2 * SA + SB)
#define SMEM_U32 (2 * SA + 2 * SB)
#define SMEM_BYTES (SMEM_U32 * 4)

__device__ __forceinline__ void mma_bf16(float& d0, float& d1, float& d2, float& d3,
                                         uint32_t a0, uint32_t a1, uint32_t a2, uint32_t a3,
                                         uint32_t b0, uint32_t b1) {
    asm volatile(
        "mma.sync.aligned.m16n8k16.row.col.f32.bf16.bf16.f32 "
        "{%0,%1,%2,%3}, {%4,%5,%6,%7}, {%8,%9}, {%0,%1,%2,%3};"
        : "+f"(d0), "+f"(d1), "+f"(d2), "+f"(d3)
        : "r"(a0), "r"(a1), "r"(a2), "r"(a3), "r"(b0), "r"(b1));
}

__global__ void __launch_bounds__(256, 2) k_gemm1(const float* __restrict__ x) {
    extern __shared__ __align__(16) uint32_t sm[];
    int t = threadIdx.x;
    int wid = t >> 5;
    int lane = t & 31;
    int g   = lane >> 2;
    int tig = lane & 3;
    int row0 = blockIdx.x * 128;
    int mrow0 = (wid >> 1) * 32;
    int ncol0 = (wid & 1) * 32;

    float acc[2][4][4];
#pragma unroll
    for (int mt = 0; mt < 2; ++mt)
#pragma unroll
        for (int nt = 0; nt < 4; ++nt)
#pragma unroll
            for (int i = 0; i < 4; ++i) acc[mt][nt][i] = 0.f;

    const uint32_t* wh = (const uint32_t*)g_w1t_hi;
    const uint32_t* wl = (const uint32_t*)g_w1t_lo;

    for (int k0 = 0; k0 < FF; k0 += KC) {
#pragma unroll
        for (int i = 0; i < 8; ++i) {
            int idx = t + i * 256;
            int row = idx >> 4;
            int c4  = (idx & 15) << 2;
            int gr  = row0 + row;
            float4 v = (gr < NN) ? *(const float4*)&x[(size_t)gr * FF + k0 + c4]
                                 : make_float4(0.f, 0.f, 0.f, 0.f);
            __nv_bfloat162 h01 = __floats2bfloat162_rn(v.x, v.y);
            __nv_bfloat162 h23 = __floats2bfloat162_rn(v.z, v.w);
            __nv_bfloat162 l01 = __floats2bfloat162_rn(v.x - __bfloat162float(__low2bfloat16(h01)),
                                                       v.y - __bfloat162float(__high2bfloat16(h01)));
            __nv_bfloat162 l23 = __floats2bfloat162_rn(v.z - __bfloat162float(__low2bfloat16(h23)),
                                                       v.w - __bfloat162float(__high2bfloat16(h23)));
            int base = row * ROWU + (c4 >> 1);
            sm[SM_AHI + base]     = *(uint32_t*)&h01;
            sm[SM_AHI + base + 1] = *(uint32_t*)&h23;
            sm[SM_ALO + base]     = *(uint32_t*)&l01;
            sm[SM_ALO + base + 1] = *(uint32_t*)&l23;
        }
#pragma unroll
        for (int i = 0; i < 8; ++i) {
            int idx = t + i * 256;
            int row = idx >> 5;
            int cp  = idx & 31;
            sm[SM_BHI + row * ROWU + cp] = wh[row * 128 + (k0 >> 1) + cp];
            sm[SM_BLO + row * ROWU + cp] = wl[row * 128 + (k0 >> 1) + cp];
        }
        __syncthreads();

#pragma unroll
        for (int ks = 0; ks < 4; ++ks) {
            int kb = ks * 8;
            uint32_t ahi[2][4], alo[2][4];
#pragma unroll
            for (int mt = 0; mt < 2; ++mt) {
                int r = mrow0 + mt * 16 + g;
                int b0 = r * ROWU + kb + tig;
                int b1 = (r + 8) * ROWU + kb + tig;
                ahi[mt][0] = sm[SM_AHI + b0];
                ahi[mt][1] = sm[SM_AHI + b1];
                ahi[mt][2] = sm[SM_AHI + b0 + 4];
                ahi[mt][3] = sm[SM_AHI + b1 + 4];
                alo[mt][0] = sm[SM_ALO + b0];
                alo[mt][1] = sm[SM_ALO + b1];
                alo[mt][2] = sm[SM_ALO + b0 + 4];
                alo[mt][3] = sm[SM_ALO + b1 + 4];
            }
#pragma unroll
            for (int nt = 0; nt < 4; ++nt) {
                int n = ncol0 + nt * 8 + g;
                int bo = n * ROWU + kb + tig;
                uint32_t bhi0 = sm[SM_BHI + bo], bhi1 = sm[SM_BHI + bo + 4];
                uint32_t blo0 = sm[SM_BLO + bo], blo1 = sm[SM_BLO + bo + 4];
#pragma unroll
                for (int mt = 0; mt < 2; ++mt) {
                    float* a = acc[mt][nt];
                    mma_bf16(a[0], a[1], a[2], a[3],
                             ahi[mt][0], ahi[mt][1], ahi[mt][2], ahi[mt][3], bhi0, bhi1);
                    mma_bf16(a[0], a[1], a[2], a[3],
                             ahi[mt][0], ahi[mt][1], ahi[mt][2], ahi[mt][3], blo0, blo1);
                    mma_bf16(a[0], a[1], a[2], a[3],
                             alo[mt][0], alo[mt][1], alo[mt][2], alo[mt][3], bhi0, bhi1);
                }
            }
        }
        __syncthreads();
    }

    // ---- store D fragments as fp16 ----
#pragma unroll
    for (int mt = 0; mt < 2; ++mt) {
#pragma unroll
        for (int nt = 0; nt < 4; ++nt) {
            int r = row0 + mrow0 + mt * 16 + g;
            int c = ncol0 + nt * 8 + tig * 2;
            float* a = acc[mt][nt];
            if (r < NN)
                *(__half2*)&g_h1[(size_t)r * HH + c] = __floats2half2_rn(a[0], a[1]);
            if (r + 8 < NN)
                *(__half2*)&g_h1[(size_t)(r + 8) * HH + c] = __floats2half2_rn(a[2], a[3]);
        }
    }
}

// ---------------- agg1 + fused GEMV (x2@W2, prescaled) -----------------------
// 2 nodes per warp: half-warp per node, lane handles 4 dims (fp16x4 = 8B).
// Epilogue: in-warp GEMV -> z[16]; store z' = dinv * z.
__global__ void __launch_bounds__(256) k_agg1(const float* __restrict__ b1,
                                              const float* __restrict__ W2) {
    __shared__ float Ws[HH][CC + 1];     // pad 17 -> 2-way conflicts max
    {
        int t = threadIdx.x;
#pragma unroll
        for (int i = t; i < HH * CC; i += 256)
            Ws[i >> 4][i & 15] = W2[i];
    }
    __syncthreads();

    int warp = (blockIdx.x * blockDim.x + threadIdx.x) >> 5;
    int lane = threadIdx.x & 31;
    int half = lane >> 4;
    int hl   = lane & 15;
    int n = warp * 2 + half;
    if (n >= NN) return;

    const uint2* h1v = (const uint2*)g_h1;   // 4 halves per uint2, 16 per row

    float di = g_dinv[n];
    uint2 hp = h1v[(size_t)n * 16 + hl];
    float2 s01 = __half22float2(*(__half2*)&hp.x);
    float2 s23 = __half22float2(*(__half2*)&hp.y);
    // acc = sum dinv[s]*h[s] + di*h[n]; x2 = relu(di*acc + b1)
    float4 acc = make_float4(di * s01.x, di * s01.y, di * s23.x, di * s23.y);

    int e  = g_start[n];
    int eE = g_start[n + 1];
#pragma unroll 4
    for (; e < eE; ++e) {
        int   s  = __ldg(&g_csr[e]);
        float ds = __ldg(&g_dinv[s]);
        uint2 rp = __ldg(&h1v[(size_t)s * 16 + hl]);
        float2 v01 = __half22float2(*(__half2*)&rp.x);
        float2 v23 = __half22float2(*(__half2*)&rp.y);
        acc.x += ds * v01.x;  acc.y += ds * v01.y;
        acc.z += ds * v23.x;  acc.w += ds * v23.y;
    }
    float4 bb = ((const float4*)b1)[hl];
    float x2v[4];
    x2v[0] = fmaxf(di * acc.x + bb.x, 0.f);
    x2v[1] = fmaxf(di * acc.y + bb.y, 0.f);
    x2v[2] = fmaxf(di * acc.z + bb.z, 0.f);
    x2v[3] = fmaxf(di * acc.w + bb.w, 0.f);

    // ---- fused GEMV: p[c] = sum_j x2v[j] * W2[4*hl+j][c] ----
    float p[16];
#pragma unroll
    for (int c = 0; c < 16; ++c) p[c] = 0.f;
#pragma unroll
    for (int j = 0; j < 4; ++j) {
        float xv = x2v[j];
        int row = hl * 4 + j;
#pragma unroll
        for (int c = 0; c < 16; ++c)
            p[c] += xv * Ws[row][c];
    }
    // ---- butterfly reduce across 16 lanes (vector halving) ----
#pragma unroll
    for (int o = 8; o >= 1; o >>= 1) {
        bool up = (hl & o) != 0;
#pragma unroll
        for (int i = 0; i < 8; ++i) {
            if (i < o) {
                float send = up ? p[i] : p[o + i];
                float other = __shfl_xor_sync(0xffffffffu, send, o, 16);
                p[i] = (up ? p[o + i] : p[i]) + other;
            }
        }
    }
    // lane hl holds z[hl]; prescale and store
    g_z[(size_t)n * CC + hl] = di * p[0];
}

// ---------------- agg2 + bias + log_softmax ---------------------------------
// z is prescaled (z' = dinv*z): out_pre = di*(sum z'[s] + z'[n]) + b2.
__global__ void k_agg2(const float* __restrict__ b2, float* __restrict__ out) {
    int warp = (blockIdx.x * blockDim.x + threadIdx.x) >> 5;
    int lane = threadIdx.x & 31;
    int half = lane >> 4;
    int c    = lane & 15;
    int n = warp * 2 + half;
    if (n >= NN) return;

    float di = g_dinv[n];
    float acc = g_z[(size_t)n * CC + c];   // self term (already prescaled)

    int e  = g_start[n];
    int eE = g_start[n + 1];
#pragma unroll 4
    for (; e < eE; ++e) {
        int s = __ldg(&g_csr[e]);
        acc += g_z[(size_t)s * CC + c];
    }
    acc = di * acc + b2[c];

    // log_softmax over 16 dims within the half-warp
    float m = acc;
#pragma unroll
    for (int o = 8; o >= 1; o >>= 1)
        m = fmaxf(m, __shfl_xor_sync(0xffffffffu, m, o, 16));
    float ex = expf(acc - m);
    float s = ex;
#pragma unroll
    for (int o = 8; o >= 1; o >>= 1)
        s += __shfl_xor_sync(0xffffffffu, s, o, 16);
    out[(size_t)n * CC + c] = acc - m - logf(s);
}

// ---------------- launch -----------------------------------------------------
// Side stream: edge chain.  Main: wsplit+gemm1 (gemm1 = 4th call -> profiled).
extern "C" void kernel_launch(void* const* d_in, const int* in_sizes, int n_in,
                              void* d_out, int out_size) {
    const float* x  = (const float*)d_in[0];
    const void*  ei = d_in[1];
    const float* W1 = (const float*)d_in[2];
    const float* b1 = (const float*)d_in[3];
    const float* W2 = (const float*)d_in[4];
    const float* b2 = (const float*)d_in[5];
    float* out = (float*)d_out;

    cudaFuncSetAttribute(k_gemm1, cudaFuncAttributeMaxDynamicSharedMemorySize, SMEM_BYTES);

    cudaStream_t side;
    cudaEvent_t evFork, evJoin;
    cudaStreamCreateWithFlags(&side, cudaStreamNonBlocking);
    cudaEventCreateWithFlags(&evFork, cudaEventDisableTiming);
    cudaEventCreateWithFlags(&evJoin, cudaEventDisableTiming);

    cudaEventRecord(evFork, cudaStreamPerThread);
    cudaStreamWaitEvent(side, evFork, 0);

    k_zero   <<<(NN + 255) / 256, 256, 0, side>>>((const int*)ei);      // 0
    k_hist   <<<(EE / 2 + 255) / 256, 256, 0, side>>>(ei);              // 1
    k_wsplit <<<(HH * FF + 255) / 256, 256>>>(W1);                      // 2 (main)
    k_gemm1  <<<(NN + 127) / 128, 256, SMEM_BYTES>>>(x);                // 3 (main) <- profiled
    k_scan1  <<<NB1, 1024, 0, side>>>();                                // 4
    k_scan23 <<<NB1, 1024, 0, side>>>();                                // 5
    k_scatter<<<(EE / 2 + 255) / 256, 256, 0, side>>>(ei);              // 6
    cudaEventRecord(evJoin, side);

    cudaStreamWaitEvent(cudaStreamPerThread, evJoin, 0);
    k_agg1  <<<(NN / 2 + 255) / 256 * 32, 256>>>(b1, W2);               // 7
    k_agg2  <<<(NN / 2 + 255) / 256 * 32, 256>>>(b2, out);              // 8
}